// round 4
// baseline (speedup 1.0000x reference)
#include <cuda_runtime.h>
#include <cuda_bf16.h>
#include <cstdint>

#define NS      65536
#define HALF    32
#define NHID    512
#define NOUT    736
#define NOUTP   768
#define KB      8
#define TB      3.0f

#define BM      128
#define BN      256
#define BKE     64
#define NTHR    256

// smem per stage: A 2 planes (128x64 bf16 = 16KB each), B 2 planes (256x64 = 32KB each)
#define SA_H    0
#define SA_L    16384
#define SB_H    32768
#define SB_L    65536
#define STAGE   98304
#define SMEM_TOTAL (2*STAGE)   // 192KB

// ================= static scratch =================
__device__ __nv_bfloat16 g_xH[(size_t)NS*64];
__device__ __nv_bfloat16 g_xL[(size_t)NS*64];
__device__ __nv_bfloat16 g_aH0[(size_t)NS*NHID];
__device__ __nv_bfloat16 g_aL0[(size_t)NS*NHID];
__device__ __nv_bfloat16 g_aH1[(size_t)NS*NHID];
__device__ __nv_bfloat16 g_aL1[(size_t)NS*NHID];
__device__ float         g_bufC[(size_t)NS*NOUTP];
__device__ __nv_bfloat16 g_w1H[2][512*64],  g_w1L[2][512*64];
__device__ __nv_bfloat16 g_w2H[2][512*512], g_w2L[2][512*512];
__device__ __nv_bfloat16 g_w3H[2][512*512], g_w3L[2][512*512];
__device__ __nv_bfloat16 g_w4H[2][768*512], g_w4L[2][768*512];
__device__ float         g_b4p[2][NOUTP];

// ================= helpers =================
__device__ __forceinline__ uint32_t smem_u32(const void* p) {
    uint32_t a;
    asm("{ .reg .u64 t; cvta.to.shared.u64 t, %1; cvt.u32.u64 %0, t; }" : "=r"(a) : "l"(p));
    return a;
}
#define SWZ(x) ((x) ^ (((x) >> 3) & 0x70))

#define CP16(dst, src) asm volatile("cp.async.cg.shared.global [%0], [%1], 16;" :: "r"(dst), "l"(src))
#define CP_COMMIT()    asm volatile("cp.async.commit_group;" ::: "memory")
#define CP_WAIT(N)     asm volatile("cp.async.wait_group %0;" :: "n"(N) : "memory")

#define LDSM4(r, a) \
    asm volatile("ldmatrix.sync.aligned.m8n8.x4.shared.b16 {%0,%1,%2,%3}, [%4];" \
        : "=r"((r)[0]), "=r"((r)[1]), "=r"((r)[2]), "=r"((r)[3]) : "r"(a))

#define MMA16816(c, a, b0, b1) \
    asm volatile("mma.sync.aligned.m16n8k16.row.col.f32.bf16.bf16.f32 " \
        "{%0,%1,%2,%3}, {%4,%5,%6,%7}, {%8,%9}, {%0,%1,%2,%3};" \
        : "+f"((c)[0]), "+f"((c)[1]), "+f"((c)[2]), "+f"((c)[3]) \
        : "r"((a)[0]), "r"((a)[1]), "r"((a)[2]), "r"((a)[3]), "r"(b0), "r"(b1))

// ================= GEMM =================
// C[M,N'] = act(A[M,K'] @ B[N',K']^T + bias); split bf16x2 operands, 3-term HMMA.
// CTA tile 128x256, warp grid 2(M) x 4(N), warp tile 64x64.
template <int KT, int ACT, int SPLIT>
__global__ void __launch_bounds__(NTHR, 1) gemm_bf16x2(
    const __nv_bfloat16* __restrict__ Ah, const __nv_bfloat16* __restrict__ Al, int lda,
    const __nv_bfloat16* __restrict__ Bh, const __nv_bfloat16* __restrict__ Bl,
    const float* __restrict__ bias,
    __nv_bfloat16* __restrict__ Ch, __nv_bfloat16* __restrict__ Cl,
    float* __restrict__ Cf, int ldc)
{
    extern __shared__ __align__(1024) char smem[];
    const uint32_t sb = smem_u32(smem);
    const int tid  = threadIdx.x;
    const int wid  = tid >> 5;
    const int l    = tid & 31;
    const int wm   = wid & 1;          // 2 warps over M -> 64 rows each
    const int wn   = wid >> 1;         // 4 warps over N -> 64 cols each
    const int row0 = blockIdx.y * BM;
    const int col0 = blockIdx.x * BN;
    const int ldb  = KT * BKE;

    float acc[4][8][4];
#pragma unroll
    for (int i = 0; i < 4; i++)
#pragma unroll
        for (int j = 0; j < 8; j++)
#pragma unroll
            for (int q = 0; q < 4; q++) acc[i][j][q] = 0.f;

    auto load_tile = [&](int s, int m) {
        const uint32_t sbase = sb + s * STAGE;
        const int koff = m * BKE;
#pragma unroll
        for (int i = 0; i < 4; i++) {            // A planes: 1024 chunks each
            int c = tid + i * NTHR;
            int r = c >> 3, q = c & 7;
            uint32_t off = SWZ(r * 128 + q * 16);
            CP16(sbase + SA_H + off, Ah + (size_t)(row0 + r) * lda + koff + q * 8);
            CP16(sbase + SA_L + off, Al + (size_t)(row0 + r) * lda + koff + q * 8);
        }
#pragma unroll
        for (int i = 0; i < 8; i++) {            // B planes: 2048 chunks each
            int c = tid + i * NTHR;
            int n = c >> 3, q = c & 7;
            uint32_t off = SWZ(n * 128 + q * 16);
            CP16(sbase + SB_H + off, Bh + (size_t)(col0 + n) * ldb + koff + q * 8);
            CP16(sbase + SB_L + off, Bl + (size_t)(col0 + n) * ldb + koff + q * 8);
        }
    };

    auto compute = [&](int s) {
        const uint32_t AhB = sb + s * STAGE + SA_H;
        const uint32_t AlB = sb + s * STAGE + SA_L;
        const uint32_t BhB = sb + s * STAGE + SB_H;
        const uint32_t BlB = sb + s * STAGE + SB_L;
#pragma unroll
        for (int ks = 0; ks < 4; ks++) {
            // B fragments: 4 n16 blocks, 2 planes
            uint32_t bh[4][4], bl[4][4];
#pragma unroll
            for (int j16 = 0; j16 < 4; j16++) {
                int n = wn * 64 + j16 * 16 + (l & 7) + ((l >> 4) << 3);
                int colb = (ks * 16 + ((l >> 3) & 1) * 8) * 2;
                uint32_t off = n * 128 + (colb ^ ((n & 7) << 4));
                LDSM4(bh[j16], BhB + off);
                LDSM4(bl[j16], BlB + off);
            }
#pragma unroll
            for (int i = 0; i < 4; i++) {
                uint32_t ah[4], al[4];
                int row = wm * 64 + i * 16 + (l & 15);
                int colb = (ks * 16 + (l >> 4) * 8) * 2;
                uint32_t off = row * 128 + (colb ^ ((row & 7) << 4));
                LDSM4(ah, AhB + off);
                LDSM4(al, AlB + off);
#pragma unroll
                for (int j16 = 0; j16 < 4; j16++)
#pragma unroll
                    for (int hf = 0; hf < 2; hf++) {
                        const int j = j16 * 2 + hf;
                        MMA16816(acc[i][j], ah, bh[j16][hf*2], bh[j16][hf*2+1]);
                        MMA16816(acc[i][j], ah, bl[j16][hf*2], bl[j16][hf*2+1]);
                        MMA16816(acc[i][j], al, bh[j16][hf*2], bh[j16][hf*2+1]);
                    }
            }
        }
    };

    load_tile(0, 0); CP_COMMIT();
#pragma unroll
    for (int kt = 0; kt < KT; kt++) {
        CP_WAIT(0);
        __syncthreads();
        if (kt + 1 < KT) { load_tile((kt + 1) & 1, kt + 1); CP_COMMIT(); }
        compute(kt & 1);
    }

    // ---- epilogue ----
#pragma unroll
    for (int i = 0; i < 4; i++) {
        const int r0 = row0 + wm * 64 + i * 16 + (l >> 2);
#pragma unroll
        for (int j = 0; j < 8; j++) {
            const int c = col0 + wn * 64 + j * 8 + (l & 3) * 2;
            const float b0 = bias[c], b1 = bias[c + 1];
            float v0 = acc[i][j][0] + b0, v1 = acc[i][j][1] + b1;
            float v2 = acc[i][j][2] + b0, v3 = acc[i][j][3] + b1;
            if (ACT) {
                v0 = (v0 > 0.f) ? v0 : 0.2f * v0;
                v1 = (v1 > 0.f) ? v1 : 0.2f * v1;
                v2 = (v2 > 0.f) ? v2 : 0.2f * v2;
                v3 = (v3 > 0.f) ? v3 : 0.2f * v3;
            }
            if (SPLIT) {
                __nv_bfloat162 h01, h23, l01, l23;
                __nv_bfloat16 h;
                h = __float2bfloat16(v0); h01.x = h; l01.x = __float2bfloat16(v0 - __bfloat162float(h));
                h = __float2bfloat16(v1); h01.y = h; l01.y = __float2bfloat16(v1 - __bfloat162float(h));
                h = __float2bfloat16(v2); h23.x = h; l23.x = __float2bfloat16(v2 - __bfloat162float(h));
                h = __float2bfloat16(v3); h23.y = h; l23.y = __float2bfloat16(v3 - __bfloat162float(h));
                *(__nv_bfloat162*)(Ch + (size_t)r0 * ldc + c)       = h01;
                *(__nv_bfloat162*)(Cl + (size_t)r0 * ldc + c)       = l01;
                *(__nv_bfloat162*)(Ch + (size_t)(r0 + 8) * ldc + c) = h23;
                *(__nv_bfloat162*)(Cl + (size_t)(r0 + 8) * ldc + c) = l23;
            } else {
                *(float2*)(Cf + (size_t)r0 * ldc + c)       = make_float2(v0, v1);
                *(float2*)(Cf + (size_t)(r0 + 8) * ldc + c) = make_float2(v2, v3);
            }
        }
    }
}

// ================= weight prep: transpose + pad + bf16 split =================
__global__ void prep_w(const float* __restrict__ W, const float* __restrict__ b,
                       int K, int N, int Kpad, int Npad,
                       __nv_bfloat16* __restrict__ WtH, __nv_bfloat16* __restrict__ WtL,
                       float* __restrict__ bpad)
{
    int idx = blockIdx.x * 256 + threadIdx.x;
    if (idx >= Npad * Kpad) return;
    int n = idx / Kpad, k = idx - n * Kpad;
    float v = (k < K && n < N) ? W[(size_t)k * N + n] : 0.f;
    __nv_bfloat16 h = __float2bfloat16(v);
    WtH[idx] = h;
    WtL[idx] = __float2bfloat16(v - __bfloat162float(h));
    if (bpad && k == 0) bpad[n] = (n < N) ? b[n] : 0.f;
}

__global__ void split_x(const float* __restrict__ x,
                        __nv_bfloat16* __restrict__ H, __nv_bfloat16* __restrict__ L)
{
    int idx = blockIdx.x * 256 + threadIdx.x;
    int s = idx >> 6, d = idx & 63;
    float v = (d < HALF) ? x[(size_t)s * 64 + d] : 0.f;
    __nv_bfloat16 h = __float2bfloat16(v);
    H[idx] = h;
    L[idx] = __float2bfloat16(v - __bfloat162float(h));
}

// ================= spline =================
__device__ __forceinline__ float softplusf(float x) {
    return (x > 0.f) ? (x + log1pf(expf(-x))) : log1pf(expf(x));
}

__global__ void __launch_bounds__(256) spline_kernel(
    const float* __restrict__ y, int ldy,
    const float* __restrict__ cond,
    float* __restrict__ out_y, int ldo,
    float* __restrict__ logdet, int add,
    __nv_bfloat16* __restrict__ upH, __nv_bfloat16* __restrict__ upL)
{
    const int gid = blockIdx.x * 256 + threadIdx.x;
    const int s   = gid >> 5;
    const int dim = gid & 31;
    if (s >= NS) return;

    const float* p = cond + (size_t)s * NOUTP + dim * 23;
    const float x = y[(size_t)s * ldy + dim];

    float rw[KB], rh[KB];
#pragma unroll
    for (int i = 0; i < KB; i++) rw[i] = p[i];
#pragma unroll
    for (int i = 0; i < KB; i++) rh[i] = p[KB + i];

    float cw[KB + 1], wid[KB];
    {
        float m = rw[0];
#pragma unroll
        for (int i = 1; i < KB; i++) m = fmaxf(m, rw[i]);
        float s1 = 0.f, e[KB];
#pragma unroll
        for (int i = 0; i < KB; i++) { e[i] = expf(rw[i] - m); s1 += e[i]; }
        float inv1 = 1.f / s1, Wv[KB];
#pragma unroll
        for (int i = 0; i < KB; i++) Wv[i] = 2.f * TB * e[i] * inv1;
        float m2 = Wv[0];
#pragma unroll
        for (int i = 1; i < KB; i++) m2 = fmaxf(m2, Wv[i]);
        float s2 = 0.f;
#pragma unroll
        for (int i = 0; i < KB; i++) { e[i] = expf(Wv[i] - m2); s2 += e[i]; }
        float inv2 = 1.f / s2;
        float run = 0.f;
        cw[0] = -TB;
#pragma unroll
        for (int i = 0; i < KB; i++) {
            float w = 0.001f + (1.f - 0.001f * KB) * e[i] * inv2;
            run += w;
            cw[i + 1] = 2.f * TB * run - TB;
        }
        cw[KB] = TB;
#pragma unroll
        for (int i = 0; i < KB; i++) wid[i] = cw[i + 1] - cw[i];
    }

    float ch[KB + 1], hei[KB];
    {
        float m = rh[0];
#pragma unroll
        for (int i = 1; i < KB; i++) m = fmaxf(m, rh[i]);
        float s1 = 0.f, e[KB];
#pragma unroll
        for (int i = 0; i < KB; i++) { e[i] = expf(rh[i] - m); s1 += e[i]; }
        float inv1 = 1.f / s1, Hv[KB];
#pragma unroll
        for (int i = 0; i < KB; i++) Hv[i] = 2.f * TB * e[i] * inv1;
        float m2 = Hv[0];
#pragma unroll
        for (int i = 1; i < KB; i++) m2 = fmaxf(m2, Hv[i]);
        float s2 = 0.f;
#pragma unroll
        for (int i = 0; i < KB; i++) { e[i] = expf(Hv[i] - m2); s2 += e[i]; }
        float inv2 = 1.f / s2;
        float run = 0.f;
        ch[0] = -TB;
#pragma unroll
        for (int i = 0; i < KB; i++) {
            float h = 0.001f + (1.f - 0.001f * KB) * e[i] * inv2;
            run += h;
            ch[i + 1] = 2.f * TB * run - TB;
        }
        ch[KB] = TB;
#pragma unroll
        for (int i = 0; i < KB; i++) hei[i] = ch[i + 1] - ch[i];
    }

    float der[KB + 1];
    {
        const float CONST = 0.5397432446f;
        der[0] = 0.001f + softplusf(CONST);
        der[KB] = der[0];
#pragma unroll
        for (int i = 0; i < KB - 1; i++)
            der[i + 1] = 0.001f + softplusf(softplusf(p[2 * KB + i]));
    }

    const bool inside = (x >= -TB) && (x <= TB);
    const float xc = fminf(fmaxf(x, -TB), TB);
    int cnt = 0;
#pragma unroll
    for (int j = 0; j <= KB; j++) {
        float ce = cw[j] + ((j == KB) ? 1e-6f : 0.f);
        cnt += (xc >= ce) ? 1 : 0;
    }
    int idx = min(max(cnt - 1, 0), KB - 1);

    float in_cw = 0.f, in_w = 1.f, in_ch = 0.f, in_h = 1.f, in_der = 1.f, in_der1 = 1.f;
#pragma unroll
    for (int j = 0; j < KB; j++) {
        if (j == idx) {
            in_cw = cw[j]; in_w = wid[j]; in_ch = ch[j]; in_h = hei[j];
            in_der = der[j]; in_der1 = der[j + 1];
        }
    }
    const float in_d = in_h / in_w;
    const float theta = (xc - in_cw) / in_w;
    const float t1mt  = theta * (1.f - theta);
    const float num   = in_h * (in_d * theta * theta + in_der * t1mt);
    const float den   = in_d + (in_der + in_der1 - 2.f * in_d) * t1mt;
    const float outv  = in_ch + num / den;
    const float omt   = 1.f - theta;
    const float dnum  = in_d * in_d * (in_der1 * theta * theta + 2.f * in_d * t1mt + in_der * omt * omt);
    float lad = logf(dnum) - 2.f * logf(den);

    const float fv = inside ? outv : x;
    out_y[(size_t)s * ldo + dim] = fv;
    lad = inside ? lad : 0.f;

    if (upH) {
        __nv_bfloat16 h = __float2bfloat16(fv);
        float rem = fv - __bfloat162float(h);
        upH[(size_t)s * 64 + dim] = h;
        upL[(size_t)s * 64 + dim] = __float2bfloat16(rem);
        upH[(size_t)s * 64 + 32 + dim] = __float2bfloat16(0.f);
        upL[(size_t)s * 64 + 32 + dim] = __float2bfloat16(0.f);
    }

#pragma unroll
    for (int off = 16; off > 0; off >>= 1)
        lad += __shfl_down_sync(0xffffffffu, lad, off);
    if (dim == 0) {
        if (add) logdet[s] += lad;
        else     logdet[s]  = lad;
    }
}

// ================= launch =================
extern "C" void kernel_launch(void* const* d_in, const int* in_sizes, int n_in,
                              void* d_out, int out_size)
{
    const float* x = (const float*)d_in[0];
    const float* w[2][4] = {{(const float*)d_in[1], (const float*)d_in[3], (const float*)d_in[5], (const float*)d_in[7]},
                            {(const float*)d_in[9], (const float*)d_in[11], (const float*)d_in[13], (const float*)d_in[15]}};
    const float* bb[2][4] = {{(const float*)d_in[2], (const float*)d_in[4], (const float*)d_in[6], (const float*)d_in[8]},
                             {(const float*)d_in[10], (const float*)d_in[12], (const float*)d_in[14], (const float*)d_in[16]}};

    float* out    = (float*)d_out;
    float* logdet = out + (size_t)NS * 64;

    __nv_bfloat16 *xH, *xL, *aH0, *aL0, *aH1, *aL1;
    __nv_bfloat16 *w1H, *w1L, *w2H, *w2L, *w3H, *w3L, *w4H, *w4L;
    float *bufC, *b4p;
    cudaGetSymbolAddress((void**)&xH, g_xH);   cudaGetSymbolAddress((void**)&xL, g_xL);
    cudaGetSymbolAddress((void**)&aH0, g_aH0); cudaGetSymbolAddress((void**)&aL0, g_aL0);
    cudaGetSymbolAddress((void**)&aH1, g_aH1); cudaGetSymbolAddress((void**)&aL1, g_aL1);
    cudaGetSymbolAddress((void**)&w1H, g_w1H); cudaGetSymbolAddress((void**)&w1L, g_w1L);
    cudaGetSymbolAddress((void**)&w2H, g_w2H); cudaGetSymbolAddress((void**)&w2L, g_w2L);
    cudaGetSymbolAddress((void**)&w3H, g_w3H); cudaGetSymbolAddress((void**)&w3L, g_w3L);
    cudaGetSymbolAddress((void**)&w4H, g_w4H); cudaGetSymbolAddress((void**)&w4L, g_w4L);
    cudaGetSymbolAddress((void**)&bufC, g_bufC);
    cudaGetSymbolAddress((void**)&b4p, g_b4p);

    cudaFuncSetAttribute(gemm_bf16x2<1,1,1>, cudaFuncAttributeMaxDynamicSharedMemorySize, SMEM_TOTAL);
    cudaFuncSetAttribute(gemm_bf16x2<8,1,1>, cudaFuncAttributeMaxDynamicSharedMemorySize, SMEM_TOTAL);
    cudaFuncSetAttribute(gemm_bf16x2<8,0,0>, cudaFuncAttributeMaxDynamicSharedMemorySize, SMEM_TOTAL);

    for (int c = 0; c < 2; c++) {
        prep_w<<<(512*64 + 255)/256, 256>>>(w[c][0], nullptr, HALF, NHID, 64, 512,
                                            w1H + c*512*64, w1L + c*512*64, nullptr);
        prep_w<<<(512*512 + 255)/256, 256>>>(w[c][1], nullptr, NHID, NHID, 512, 512,
                                             w2H + c*512*512, w2L + c*512*512, nullptr);
        prep_w<<<(512*512 + 255)/256, 256>>>(w[c][2], nullptr, NHID, NHID, 512, 512,
                                             w3H + c*512*512, w3L + c*512*512, nullptr);
        prep_w<<<(768*512 + 255)/256, 256>>>(w[c][3], bb[c][3], NHID, NOUT, 512, NOUTP,
                                             w4H + c*768*512, w4L + c*768*512, b4p + c*NOUTP);
    }
    split_x<<<(NS*64)/256, 256>>>(x, xH, xL);

    const dim3 blk(NTHR);
    const dim3 g512(NHID / BN, NS / BM);   // (2, 512)
    const dim3 g768(NOUTP / BN, NS / BM);  // (3, 512)
    const int splineBlocks = (NS * 32) / 256;

    for (int c = 0; c < 2; c++) {
        gemm_bf16x2<1,1,1><<<g512, blk, SMEM_TOTAL>>>(xH, xL, 64,
            w1H + c*512*64, w1L + c*512*64, bb[c][0], aH0, aL0, nullptr, NHID);
        gemm_bf16x2<8,1,1><<<g512, blk, SMEM_TOTAL>>>(aH0, aL0, NHID,
            w2H + c*512*512, w2L + c*512*512, bb[c][1], aH1, aL1, nullptr, NHID);
        gemm_bf16x2<8,1,1><<<g512, blk, SMEM_TOTAL>>>(aH1, aL1, NHID,
            w3H + c*512*512, w3L + c*512*512, bb[c][2], aH0, aL0, nullptr, NHID);
        gemm_bf16x2<8,0,0><<<g768, blk, SMEM_TOTAL>>>(aH0, aL0, NHID,
            w4H + c*768*512, w4L + c*768*512, b4p + c*NOUTP, nullptr, nullptr, bufC, NOUTP);
        if (c == 0)
            spline_kernel<<<splineBlocks, blk>>>(x + HALF, 64, bufC, out + HALF, 64, logdet, 0, xH, xL);
        else
            spline_kernel<<<splineBlocks, blk>>>(x, 64, bufC, out, 64, logdet, 1, nullptr, nullptr);
    }
}

// round 5
// speedup vs baseline: 1.0078x; 1.0078x over previous
#include <cuda_runtime.h>
#include <cuda_bf16.h>
#include <cstdint>

#define NS      65536
#define HALF    32
#define NHID    512
#define NOUT    736
#define NOUTP   768
#define KB      8
#define TB      3.0f

#define BM      128
#define BN      256
#define BKE     64
#define NTHR    256

#define SA_H    0
#define SA_L    16384
#define SB_H    32768
#define SB_L    65536
#define STAGE   98304
#define SMEM_TOTAL (2*STAGE)   // 192KB

// ================= static scratch =================
__device__ __nv_bfloat16 g_xH[(size_t)NS*64];
__device__ __nv_bfloat16 g_xL[(size_t)NS*64];
__device__ __nv_bfloat16 g_aH0[(size_t)NS*NHID];
__device__ __nv_bfloat16 g_aL0[(size_t)NS*NHID];
__device__ __nv_bfloat16 g_aH1[(size_t)NS*NHID];
__device__ __nv_bfloat16 g_aL1[(size_t)NS*NHID];
__device__ float         g_bufC[(size_t)NS*NOUTP];
__device__ __nv_bfloat16 g_w1H[2][512*64],  g_w1L[2][512*64];
__device__ __nv_bfloat16 g_w2H[2][512*512], g_w2L[2][512*512];
__device__ __nv_bfloat16 g_w3H[2][512*512], g_w3L[2][512*512];
__device__ __nv_bfloat16 g_w4H[2][768*512], g_w4L[2][768*512];
__device__ float         g_b4p[2][NOUTP];

// ================= helpers =================
__device__ __forceinline__ uint32_t smem_u32(const void* p) {
    uint32_t a;
    asm("{ .reg .u64 t; cvta.to.shared.u64 t, %1; cvt.u32.u64 %0, t; }" : "=r"(a) : "l"(p));
    return a;
}
#define SWZ(x) ((x) ^ (((x) >> 3) & 0x70))

#define CP16(dst, src) asm volatile("cp.async.cg.shared.global [%0], [%1], 16;" :: "r"(dst), "l"(src))
#define CP_COMMIT()    asm volatile("cp.async.commit_group;" ::: "memory")
#define CP_WAIT(N)     asm volatile("cp.async.wait_group %0;" :: "n"(N) : "memory")

#define LDSM4(r, a) \
    asm volatile("ldmatrix.sync.aligned.m8n8.x4.shared.b16 {%0,%1,%2,%3}, [%4];" \
        : "=r"((r)[0]), "=r"((r)[1]), "=r"((r)[2]), "=r"((r)[3]) : "r"(a))

#define MMA16816(c, a, b0, b1) \
    asm volatile("mma.sync.aligned.m16n8k16.row.col.f32.bf16.bf16.f32 " \
        "{%0,%1,%2,%3}, {%4,%5,%6,%7}, {%8,%9}, {%0,%1,%2,%3};" \
        : "+f"((c)[0]), "+f"((c)[1]), "+f"((c)[2]), "+f"((c)[3]) \
        : "r"((a)[0]), "r"((a)[1]), "r"((a)[2]), "r"((a)[3]), "r"(b0), "r"(b1))

// ================= GEMM =================
// C[M,N'] = act(A[M,K'] @ B[N',K']^T + bias); split bf16x2 operands, 3-term HMMA,
// term-major ordering (32 independent MMAs between dependent writes to an acc).
template <int KT, int ACT, int SPLIT>
__global__ void __launch_bounds__(NTHR, 1) gemm_bf16x2(
    const __nv_bfloat16* __restrict__ Ah, const __nv_bfloat16* __restrict__ Al, int lda,
    const __nv_bfloat16* __restrict__ Bh, const __nv_bfloat16* __restrict__ Bl,
    const float* __restrict__ bias,
    __nv_bfloat16* __restrict__ Ch, __nv_bfloat16* __restrict__ Cl,
    float* __restrict__ Cf, int ldc)
{
    extern __shared__ __align__(1024) char smem[];
    const uint32_t sb = smem_u32(smem);
    const int tid  = threadIdx.x;
    const int wid  = tid >> 5;
    const int l    = tid & 31;
    const int wm   = wid & 1;          // 2 warps over M -> 64 rows each
    const int wn   = wid >> 1;         // 4 warps over N -> 64 cols each
    const int row0 = blockIdx.y * BM;
    const int col0 = blockIdx.x * BN;
    const int ldb  = KT * BKE;

    float acc[4][8][4];
#pragma unroll
    for (int i = 0; i < 4; i++)
#pragma unroll
        for (int j = 0; j < 8; j++)
#pragma unroll
            for (int q = 0; q < 4; q++) acc[i][j][q] = 0.f;

    auto load_tile = [&](int s, int m) {
        const uint32_t sbase = sb + s * STAGE;
        const int koff = m * BKE;
#pragma unroll
        for (int i = 0; i < 4; i++) {
            int c = tid + i * NTHR;
            int r = c >> 3, q = c & 7;
            uint32_t off = SWZ(r * 128 + q * 16);
            CP16(sbase + SA_H + off, Ah + (size_t)(row0 + r) * lda + koff + q * 8);
            CP16(sbase + SA_L + off, Al + (size_t)(row0 + r) * lda + koff + q * 8);
        }
#pragma unroll
        for (int i = 0; i < 8; i++) {
            int c = tid + i * NTHR;
            int n = c >> 3, q = c & 7;
            uint32_t off = SWZ(n * 128 + q * 16);
            CP16(sbase + SB_H + off, Bh + (size_t)(col0 + n) * ldb + koff + q * 8);
            CP16(sbase + SB_L + off, Bl + (size_t)(col0 + n) * ldb + koff + q * 8);
        }
    };

    auto compute = [&](int s) {
        const uint32_t AhB = sb + s * STAGE + SA_H;
        const uint32_t AlB = sb + s * STAGE + SA_L;
        const uint32_t BhB = sb + s * STAGE + SB_H;
        const uint32_t BlB = sb + s * STAGE + SB_L;
#pragma unroll
        for (int ks = 0; ks < 4; ks++) {
            // load ALL fragments for this k16-slice first
            uint32_t ah[4][4], al[4][4], bh[4][4], bl[4][4];
#pragma unroll
            for (int j16 = 0; j16 < 4; j16++) {
                int n = wn * 64 + j16 * 16 + (l & 7) + ((l >> 4) << 3);
                int colb = (ks * 16 + ((l >> 3) & 1) * 8) * 2;
                uint32_t off = n * 128 + (colb ^ ((n & 7) << 4));
                LDSM4(bh[j16], BhB + off);
                LDSM4(bl[j16], BlB + off);
            }
#pragma unroll
            for (int i = 0; i < 4; i++) {
                int row = wm * 64 + i * 16 + (l & 15);
                int colb = (ks * 16 + (l >> 4) * 8) * 2;
                uint32_t off = row * 128 + (colb ^ ((row & 7) << 4));
                LDSM4(ah[i], AhB + off);
                LDSM4(al[i], AlB + off);
            }
            // term-major: 32 hh, then 32 hl, then 32 lh
#pragma unroll
            for (int i = 0; i < 4; i++)
#pragma unroll
                for (int j16 = 0; j16 < 4; j16++)
#pragma unroll
                    for (int hf = 0; hf < 2; hf++)
                        MMA16816(acc[i][j16 * 2 + hf], ah[i], bh[j16][hf*2], bh[j16][hf*2+1]);
#pragma unroll
            for (int i = 0; i < 4; i++)
#pragma unroll
                for (int j16 = 0; j16 < 4; j16++)
#pragma unroll
                    for (int hf = 0; hf < 2; hf++)
                        MMA16816(acc[i][j16 * 2 + hf], ah[i], bl[j16][hf*2], bl[j16][hf*2+1]);
#pragma unroll
            for (int i = 0; i < 4; i++)
#pragma unroll
                for (int j16 = 0; j16 < 4; j16++)
#pragma unroll
                    for (int hf = 0; hf < 2; hf++)
                        MMA16816(acc[i][j16 * 2 + hf], al[i], bh[j16][hf*2], bh[j16][hf*2+1]);
        }
    };

    load_tile(0, 0); CP_COMMIT();
#pragma unroll
    for (int kt = 0; kt < KT; kt++) {
        CP_WAIT(0);
        __syncthreads();
        if (kt + 1 < KT) { load_tile((kt + 1) & 1, kt + 1); CP_COMMIT(); }
        compute(kt & 1);
    }

    // ---- epilogue ----
#pragma unroll
    for (int i = 0; i < 4; i++) {
        const int r0 = row0 + wm * 64 + i * 16 + (l >> 2);
#pragma unroll
        for (int j = 0; j < 8; j++) {
            const int c = col0 + wn * 64 + j * 8 + (l & 3) * 2;
            const float b0 = bias[c], b1 = bias[c + 1];
            float v0 = acc[i][j][0] + b0, v1 = acc[i][j][1] + b1;
            float v2 = acc[i][j][2] + b0, v3 = acc[i][j][3] + b1;
            if (ACT) {
                v0 = (v0 > 0.f) ? v0 : 0.2f * v0;
                v1 = (v1 > 0.f) ? v1 : 0.2f * v1;
                v2 = (v2 > 0.f) ? v2 : 0.2f * v2;
                v3 = (v3 > 0.f) ? v3 : 0.2f * v3;
            }
            if (SPLIT) {
                __nv_bfloat162 h01, h23, l01, l23;
                __nv_bfloat16 h;
                h = __float2bfloat16(v0); h01.x = h; l01.x = __float2bfloat16(v0 - __bfloat162float(h));
                h = __float2bfloat16(v1); h01.y = h; l01.y = __float2bfloat16(v1 - __bfloat162float(h));
                h = __float2bfloat16(v2); h23.x = h; l23.x = __float2bfloat16(v2 - __bfloat162float(h));
                h = __float2bfloat16(v3); h23.y = h; l23.y = __float2bfloat16(v3 - __bfloat162float(h));
                *(__nv_bfloat162*)(Ch + (size_t)r0 * ldc + c)       = h01;
                *(__nv_bfloat162*)(Cl + (size_t)r0 * ldc + c)       = l01;
                *(__nv_bfloat162*)(Ch + (size_t)(r0 + 8) * ldc + c) = h23;
                *(__nv_bfloat162*)(Cl + (size_t)(r0 + 8) * ldc + c) = l23;
            } else {
                *(float2*)(Cf + (size_t)r0 * ldc + c)       = make_float2(v0, v1);
                *(float2*)(Cf + (size_t)(r0 + 8) * ldc + c) = make_float2(v2, v3);
            }
        }
    }
}

// ================= merged weight prep =================
struct PrepArgs {
    const float* W[8];
    const float* b4[2];
    __nv_bfloat16* H[8];
    __nv_bfloat16* L[8];
    float* bp[2];
};

#define PREP_TOTAL 1900544   // 2 * (32768 + 262144 + 262144 + 393216)

__global__ void prep_all(PrepArgs a)
{
    int idx = blockIdx.x * 256 + threadIdx.x;
    if (idx >= PREP_TOTAL) return;
    int c = 0, off = idx;
    if (off >= 950272) { c = 1; off -= 950272; }
    int seg, K, N, Kpad, Npad;
    if (off < 32768)       { seg = 0; K = 32;  N = 512; Kpad = 64;  Npad = 512; }
    else if (off < 294912) { seg = 1; off -= 32768;  K = 512; N = 512; Kpad = 512; Npad = 512; }
    else if (off < 557056) { seg = 2; off -= 294912; K = 512; N = 512; Kpad = 512; Npad = 512; }
    else                   { seg = 3; off -= 557056; K = 512; N = 736; Kpad = 512; Npad = 768; }
    const int widx = c * 4 + seg;
    const int n = off / Kpad, k = off - n * Kpad;
    float v = (k < K && n < N) ? a.W[widx][(size_t)k * N + n] : 0.f;
    __nv_bfloat16 h = __float2bfloat16(v);
    a.H[widx][off] = h;
    a.L[widx][off] = __float2bfloat16(v - __bfloat162float(h));
    if (seg == 3 && k == 0) a.bp[c][n] = (n < N) ? a.b4[c][n] : 0.f;
}

__global__ void split_x(const float* __restrict__ x,
                        __nv_bfloat16* __restrict__ H, __nv_bfloat16* __restrict__ L)
{
    int idx = blockIdx.x * 256 + threadIdx.x;
    int s = idx >> 6, d = idx & 63;
    float v = (d < HALF) ? x[(size_t)s * 64 + d] : 0.f;
    __nv_bfloat16 h = __float2bfloat16(v);
    H[idx] = h;
    L[idx] = __float2bfloat16(v - __bfloat162float(h));
}

// ================= spline =================
__device__ __forceinline__ float softplusf(float x) {
    return (x > 0.f) ? (x + log1pf(expf(-x))) : log1pf(expf(x));
}

__global__ void __launch_bounds__(256) spline_kernel(
    const float* __restrict__ y, int ldy,
    const float* __restrict__ cond,
    float* __restrict__ out_y, int ldo,
    float* __restrict__ logdet, int add,
    __nv_bfloat16* __restrict__ upH, __nv_bfloat16* __restrict__ upL)
{
    const int gid = blockIdx.x * 256 + threadIdx.x;
    const int s   = gid >> 5;
    const int dim = gid & 31;
    if (s >= NS) return;

    const float* p = cond + (size_t)s * NOUTP + dim * 23;
    const float x = y[(size_t)s * ldy + dim];

    float rw[KB], rh[KB];
#pragma unroll
    for (int i = 0; i < KB; i++) rw[i] = p[i];
#pragma unroll
    for (int i = 0; i < KB; i++) rh[i] = p[KB + i];

    float cw[KB + 1], wid[KB];
    {
        float m = rw[0];
#pragma unroll
        for (int i = 1; i < KB; i++) m = fmaxf(m, rw[i]);
        float s1 = 0.f, e[KB];
#pragma unroll
        for (int i = 0; i < KB; i++) { e[i] = expf(rw[i] - m); s1 += e[i]; }
        float inv1 = 1.f / s1, Wv[KB];
#pragma unroll
        for (int i = 0; i < KB; i++) Wv[i] = 2.f * TB * e[i] * inv1;
        float m2 = Wv[0];
#pragma unroll
        for (int i = 1; i < KB; i++) m2 = fmaxf(m2, Wv[i]);
        float s2 = 0.f;
#pragma unroll
        for (int i = 0; i < KB; i++) { e[i] = expf(Wv[i] - m2); s2 += e[i]; }
        float inv2 = 1.f / s2;
        float run = 0.f;
        cw[0] = -TB;
#pragma unroll
        for (int i = 0; i < KB; i++) {
            float w = 0.001f + (1.f - 0.001f * KB) * e[i] * inv2;
            run += w;
            cw[i + 1] = 2.f * TB * run - TB;
        }
        cw[KB] = TB;
#pragma unroll
        for (int i = 0; i < KB; i++) wid[i] = cw[i + 1] - cw[i];
    }

    float ch[KB + 1], hei[KB];
    {
        float m = rh[0];
#pragma unroll
        for (int i = 1; i < KB; i++) m = fmaxf(m, rh[i]);
        float s1 = 0.f, e[KB];
#pragma unroll
        for (int i = 0; i < KB; i++) { e[i] = expf(rh[i] - m); s1 += e[i]; }
        float inv1 = 1.f / s1, Hv[KB];
#pragma unroll
        for (int i = 0; i < KB; i++) Hv[i] = 2.f * TB * e[i] * inv1;
        float m2 = Hv[0];
#pragma unroll
        for (int i = 1; i < KB; i++) m2 = fmaxf(m2, Hv[i]);
        float s2 = 0.f;
#pragma unroll
        for (int i = 0; i < KB; i++) { e[i] = expf(Hv[i] - m2); s2 += e[i]; }
        float inv2 = 1.f / s2;
        float run = 0.f;
        ch[0] = -TB;
#pragma unroll
        for (int i = 0; i < KB; i++) {
            float h = 0.001f + (1.f - 0.001f * KB) * e[i] * inv2;
            run += h;
            ch[i + 1] = 2.f * TB * run - TB;
        }
        ch[KB] = TB;
#pragma unroll
        for (int i = 0; i < KB; i++) hei[i] = ch[i + 1] - ch[i];
    }

    float der[KB + 1];
    {
        const float CONST = 0.5397432446f;
        der[0] = 0.001f + softplusf(CONST);
        der[KB] = der[0];
#pragma unroll
        for (int i = 0; i < KB - 1; i++)
            der[i + 1] = 0.001f + softplusf(softplusf(p[2 * KB + i]));
    }

    const bool inside = (x >= -TB) && (x <= TB);
    const float xc = fminf(fmaxf(x, -TB), TB);
    int cnt = 0;
#pragma unroll
    for (int j = 0; j <= KB; j++) {
        float ce = cw[j] + ((j == KB) ? 1e-6f : 0.f);
        cnt += (xc >= ce) ? 1 : 0;
    }
    int idx = min(max(cnt - 1, 0), KB - 1);

    float in_cw = 0.f, in_w = 1.f, in_ch = 0.f, in_h = 1.f, in_der = 1.f, in_der1 = 1.f;
#pragma unroll
    for (int j = 0; j < KB; j++) {
        if (j == idx) {
            in_cw = cw[j]; in_w = wid[j]; in_ch = ch[j]; in_h = hei[j];
            in_der = der[j]; in_der1 = der[j + 1];
        }
    }
    const float in_d = in_h / in_w;
    const float theta = (xc - in_cw) / in_w;
    const float t1mt  = theta * (1.f - theta);
    const float num   = in_h * (in_d * theta * theta + in_der * t1mt);
    const float den   = in_d + (in_der + in_der1 - 2.f * in_d) * t1mt;
    const float outv  = in_ch + num / den;
    const float omt   = 1.f - theta;
    const float dnum  = in_d * in_d * (in_der1 * theta * theta + 2.f * in_d * t1mt + in_der * omt * omt);
    float lad = logf(dnum) - 2.f * logf(den);

    const float fv = inside ? outv : x;
    out_y[(size_t)s * ldo + dim] = fv;
    lad = inside ? lad : 0.f;

    if (upH) {
        __nv_bfloat16 h = __float2bfloat16(fv);
        float rem = fv - __bfloat162float(h);
        upH[(size_t)s * 64 + dim] = h;
        upL[(size_t)s * 64 + dim] = __float2bfloat16(rem);
        upH[(size_t)s * 64 + 32 + dim] = __float2bfloat16(0.f);
        upL[(size_t)s * 64 + 32 + dim] = __float2bfloat16(0.f);
    }

#pragma unroll
    for (int off = 16; off > 0; off >>= 1)
        lad += __shfl_down_sync(0xffffffffu, lad, off);
    if (dim == 0) {
        if (add) logdet[s] += lad;
        else     logdet[s]  = lad;
    }
}

// ================= launch =================
extern "C" void kernel_launch(void* const* d_in, const int* in_sizes, int n_in,
                              void* d_out, int out_size)
{
    const float* x = (const float*)d_in[0];
    const float* w[2][4] = {{(const float*)d_in[1], (const float*)d_in[3], (const float*)d_in[5], (const float*)d_in[7]},
                            {(const float*)d_in[9], (const float*)d_in[11], (const float*)d_in[13], (const float*)d_in[15]}};
    const float* bb[2][4] = {{(const float*)d_in[2], (const float*)d_in[4], (const float*)d_in[6], (const float*)d_in[8]},
                             {(const float*)d_in[10], (const float*)d_in[12], (const float*)d_in[14], (const float*)d_in[16]}};

    float* out    = (float*)d_out;
    float* logdet = out + (size_t)NS * 64;

    __nv_bfloat16 *xH, *xL, *aH0, *aL0, *aH1, *aL1;
    __nv_bfloat16 *w1H, *w1L, *w2H, *w2L, *w3H, *w3L, *w4H, *w4L;
    float *bufC, *b4p;
    cudaGetSymbolAddress((void**)&xH, g_xH);   cudaGetSymbolAddress((void**)&xL, g_xL);
    cudaGetSymbolAddress((void**)&aH0, g_aH0); cudaGetSymbolAddress((void**)&aL0, g_aL0);
    cudaGetSymbolAddress((void**)&aH1, g_aH1); cudaGetSymbolAddress((void**)&aL1, g_aL1);
    cudaGetSymbolAddress((void**)&w1H, g_w1H); cudaGetSymbolAddress((void**)&w1L, g_w1L);
    cudaGetSymbolAddress((void**)&w2H, g_w2H); cudaGetSymbolAddress((void**)&w2L, g_w2L);
    cudaGetSymbolAddress((void**)&w3H, g_w3H); cudaGetSymbolAddress((void**)&w3L, g_w3L);
    cudaGetSymbolAddress((void**)&w4H, g_w4H); cudaGetSymbolAddress((void**)&w4L, g_w4L);
    cudaGetSymbolAddress((void**)&bufC, g_bufC);
    cudaGetSymbolAddress((void**)&b4p, g_b4p);

    cudaFuncSetAttribute(gemm_bf16x2<1,1,1>, cudaFuncAttributeMaxDynamicSharedMemorySize, SMEM_TOTAL);
    cudaFuncSetAttribute(gemm_bf16x2<8,1,1>, cudaFuncAttributeMaxDynamicSharedMemorySize, SMEM_TOTAL);
    cudaFuncSetAttribute(gemm_bf16x2<8,0,0>, cudaFuncAttributeMaxDynamicSharedMemorySize, SMEM_TOTAL);

    PrepArgs pa;
    for (int c = 0; c < 2; c++) {
        for (int s = 0; s < 4; s++) pa.W[c*4 + s] = w[c][s];
        pa.b4[c] = bb[c][3];
        pa.H[c*4 + 0] = w1H + c*512*64;  pa.L[c*4 + 0] = w1L + c*512*64;
        pa.H[c*4 + 1] = w2H + c*512*512; pa.L[c*4 + 1] = w2L + c*512*512;
        pa.H[c*4 + 2] = w3H + c*512*512; pa.L[c*4 + 2] = w3L + c*512*512;
        pa.H[c*4 + 3] = w4H + c*768*512; pa.L[c*4 + 3] = w4L + c*768*512;
        pa.bp[c] = b4p + c*NOUTP;
    }
    prep_all<<<(PREP_TOTAL + 255)/256, 256>>>(pa);
    split_x<<<(NS*64)/256, 256>>>(x, xH, xL);

    const dim3 blk(NTHR);
    const dim3 g512(NHID / BN, NS / BM);   // (2, 512)
    const dim3 g768(NOUTP / BN, NS / BM);  // (3, 512)
    const int splineBlocks = (NS * 32) / 256;

    for (int c = 0; c < 2; c++) {
        gemm_bf16x2<1,1,1><<<g512, blk, SMEM_TOTAL>>>(xH, xL, 64,
            w1H + c*512*64, w1L + c*512*64, bb[c][0], aH0, aL0, nullptr, NHID);
        gemm_bf16x2<8,1,1><<<g512, blk, SMEM_TOTAL>>>(aH0, aL0, NHID,
            w2H + c*512*512, w2L + c*512*512, bb[c][1], aH1, aL1, nullptr, NHID);
        gemm_bf16x2<8,1,1><<<g512, blk, SMEM_TOTAL>>>(aH1, aL1, NHID,
            w3H + c*512*512, w3L + c*512*512, bb[c][2], aH0, aL0, nullptr, NHID);
        gemm_bf16x2<8,0,0><<<g768, blk, SMEM_TOTAL>>>(aH0, aL0, NHID,
            w4H + c*768*512, w4L + c*768*512, b4p + c*NOUTP, nullptr, nullptr, bufC, NOUTP);
        if (c == 0)
            spline_kernel<<<splineBlocks, blk>>>(x + HALF, 64, bufC, out + HALF, 64, logdet, 0, xH, xL);
        else
            spline_kernel<<<splineBlocks, blk>>>(x, 64, bufC, out, 64, logdet, 1, nullptr, nullptr);
    }
}

// round 9
// speedup vs baseline: 1.0822x; 1.0738x over previous
#include <cuda_runtime.h>
#include <cuda_bf16.h>
#include <cstdint>

#define NS      65536
#define HALF    32
#define NHID    512
#define NOUT    736
#define NOUTP   768
#define KB      8
#define TB      3.0f

#define BM      128
#define BN      128
#define BKE     32
#define NTHR    128

// stage: A 128 rows x 128B (hi|lo packed), B 128 rows x 128B => 32KB; 3 stages
#define SA      0
#define SB      16384
#define STAGE   32768
#define SMEM_TOTAL (3*STAGE)   // 96KB -> 2 CTAs/SM

// ================= static scratch =================
__device__ __nv_bfloat16 g_xH[(size_t)NS*64];
__device__ __nv_bfloat16 g_xL[(size_t)NS*64];
__device__ __nv_bfloat16 g_aH0[(size_t)NS*NHID];
__device__ __nv_bfloat16 g_aL0[(size_t)NS*NHID];
__device__ __nv_bfloat16 g_aH1[(size_t)NS*NHID];
__device__ __nv_bfloat16 g_aL1[(size_t)NS*NHID];
__device__ float         g_bufC[(size_t)NS*NOUTP];
__device__ __nv_bfloat16 g_w1H[2][512*64],  g_w1L[2][512*64];
__device__ __nv_bfloat16 g_w2H[2][512*512], g_w2L[2][512*512];
__device__ __nv_bfloat16 g_w3H[2][512*512], g_w3L[2][512*512];
__device__ __nv_bfloat16 g_w4H[2][768*512], g_w4L[2][768*512];
__device__ float         g_b4p[2][NOUTP];

// ================= helpers =================
__device__ __forceinline__ uint32_t smem_u32(const void* p) {
    uint32_t a;
    asm("{ .reg .u64 t; cvta.to.shared.u64 t, %1; cvt.u32.u64 %0, t; }" : "=r"(a) : "l"(p));
    return a;
}
#define SWZ(x) ((x) ^ (((x) >> 3) & 0x70))

#define CP16(dst, src) asm volatile("cp.async.cg.shared.global [%0], [%1], 16;" :: "r"(dst), "l"(src))
#define CP_COMMIT()    asm volatile("cp.async.commit_group;" ::: "memory")
#define CP_WAIT(N)     asm volatile("cp.async.wait_group %0;" :: "n"(N) : "memory")

#define LDSM4(r, a) \
    asm volatile("ldmatrix.sync.aligned.m8n8.x4.shared.b16 {%0,%1,%2,%3}, [%4];" \
        : "=r"((r)[0]), "=r"((r)[1]), "=r"((r)[2]), "=r"((r)[3]) : "r"(a))

#define MMA16816(c, a, b0, b1) \
    asm volatile("mma.sync.aligned.m16n8k16.row.col.f32.bf16.bf16.f32 " \
        "{%0,%1,%2,%3}, {%4,%5,%6,%7}, {%8,%9}, {%0,%1,%2,%3};" \
        : "+f"((c)[0]), "+f"((c)[1]), "+f"((c)[2]), "+f"((c)[3]) \
        : "r"((a)[0]), "r"((a)[1]), "r"((a)[2]), "r"((a)[3]), "r"(b0), "r"(b1))

// ================= GEMM =================
// C[M,N'] = act(A[M,K'] @ B[N',K']^T + bias); split bf16x2 operands, 3-term HMMA.
// 128x128 tile, 4 warps (2x2, 64x64 each), BKE=32, 3-stage ring, 2 CTAs/SM.
template <int KT, int ACT, int SPLIT>
__global__ void __launch_bounds__(NTHR, 2) gemm_bf16x2(
    const __nv_bfloat16* __restrict__ Ah, const __nv_bfloat16* __restrict__ Al, int lda,
    const __nv_bfloat16* __restrict__ Bh, const __nv_bfloat16* __restrict__ Bl,
    const float* __restrict__ bias,
    __nv_bfloat16* __restrict__ Ch, __nv_bfloat16* __restrict__ Cl,
    float* __restrict__ Cf, int ldc)
{
    extern __shared__ __align__(1024) char smem[];
    const uint32_t sb = smem_u32(smem);
    const int tid  = threadIdx.x;
    const int wid  = tid >> 5;
    const int l    = tid & 31;
    const int wm   = wid & 1;          // 2 warps over M -> 64 rows
    const int wn   = wid >> 1;         // 2 warps over N -> 64 cols
    const int row0 = blockIdx.y * BM;
    const int col0 = blockIdx.x * BN;
    const int ldb  = KT * BKE;

    float acc[4][8][4];
#pragma unroll
    for (int i = 0; i < 4; i++)
#pragma unroll
        for (int j = 0; j < 8; j++)
#pragma unroll
            for (int q = 0; q < 4; q++) acc[i][j][q] = 0.f;

    // tile loader: 128 rows, row = [hi(4x16B) | lo(4x16B)]
    auto load_tile = [&](int s, int m) {
        const uint32_t sbase = sb + s * STAGE;
        const int koff = m * BKE;
#pragma unroll
        for (int i = 0; i < 4; i++) {
            int c = tid + i * NTHR;          // 0..511
            int r = c >> 2, q = c & 3;
            uint32_t offH = SWZ(r * 128 + q * 16);
            uint32_t offL = SWZ(r * 128 + 64 + q * 16);
            const size_t ga = (size_t)(row0 + r) * lda + koff + q * 8;
            CP16(sbase + SA + offH, Ah + ga);
            CP16(sbase + SA + offL, Al + ga);
            const size_t gb = (size_t)(col0 + r) * ldb + koff + q * 8;
            CP16(sbase + SB + offH, Bh + gb);
            CP16(sbase + SB + offL, Bl + gb);
        }
    };

    auto compute = [&](int s) {
        const uint32_t AB = sb + s * STAGE + SA;
        const uint32_t BB = sb + s * STAGE + SB;
#pragma unroll
        for (int ks = 0; ks < 2; ks++) {
            uint32_t ah[4][4], al[4][4], bh[4][4], bl[4][4];
#pragma unroll
            for (int j16 = 0; j16 < 4; j16++) {
                int n = wn * 64 + j16 * 16 + (l & 7) + ((l >> 4) << 3);
                int colb = ks * 32 + ((l >> 3) & 1) * 16;
                uint32_t sw = (uint32_t)((n & 7) << 4);
                LDSM4(bh[j16], BB + n * 128 + (colb ^ sw));
                LDSM4(bl[j16], BB + n * 128 + ((64 + colb) ^ sw));
            }
#pragma unroll
            for (int i = 0; i < 4; i++) {
                int row = wm * 64 + i * 16 + (l & 15);
                int colb = ks * 32 + (l >> 4) * 16;
                uint32_t sw = (uint32_t)((row & 7) << 4);
                LDSM4(ah[i], AB + row * 128 + (colb ^ sw));
                LDSM4(al[i], AB + row * 128 + ((64 + colb) ^ sw));
            }
            // term-major: hh, hl, lh
#pragma unroll
            for (int i = 0; i < 4; i++)
#pragma unroll
                for (int j16 = 0; j16 < 4; j16++)
#pragma unroll
                    for (int hf = 0; hf < 2; hf++)
                        MMA16816(acc[i][j16 * 2 + hf], ah[i], bh[j16][hf*2], bh[j16][hf*2+1]);
#pragma unroll
            for (int i = 0; i < 4; i++)
#pragma unroll
                for (int j16 = 0; j16 < 4; j16++)
#pragma unroll
                    for (int hf = 0; hf < 2; hf++)
                        MMA16816(acc[i][j16 * 2 + hf], ah[i], bl[j16][hf*2], bl[j16][hf*2+1]);
#pragma unroll
            for (int i = 0; i < 4; i++)
#pragma unroll
                for (int j16 = 0; j16 < 4; j16++)
#pragma unroll
                    for (int hf = 0; hf < 2; hf++)
                        MMA16816(acc[i][j16 * 2 + hf], al[i], bh[j16][hf*2], bh[j16][hf*2+1]);
        }
    };

    // 3-stage pipeline
    load_tile(0, 0); CP_COMMIT();
    if (KT > 1) { load_tile(1, 1); CP_COMMIT(); }
#pragma unroll
    for (int kt = 0; kt < KT; kt++) {
        if (kt < KT - 1) CP_WAIT(1); else CP_WAIT(0);
        __syncthreads();
        if (kt + 2 < KT) { load_tile((kt + 2) % 3, kt + 2); CP_COMMIT(); }
        compute(kt % 3);
    }

    // ---- epilogue ----
#pragma unroll
    for (int i = 0; i < 4; i++) {
        const int r0 = row0 + wm * 64 + i * 16 + (l >> 2);
#pragma unroll
        for (int j = 0; j < 8; j++) {
            const int c = col0 + wn * 64 + j * 8 + (l & 3) * 2;
            const float b0 = bias[c], b1 = bias[c + 1];
            float v0 = acc[i][j][0] + b0, v1 = acc[i][j][1] + b1;
            float v2 = acc[i][j][2] + b0, v3 = acc[i][j][3] + b1;
            if (ACT) {
                v0 = (v0 > 0.f) ? v0 : 0.2f * v0;
                v1 = (v1 > 0.f) ? v1 : 0.2f * v1;
                v2 = (v2 > 0.f) ? v2 : 0.2f * v2;
                v3 = (v3 > 0.f) ? v3 : 0.2f * v3;
            }
            if (SPLIT) {
                __nv_bfloat162 h01, h23, l01, l23;
                __nv_bfloat16 h;
                h = __float2bfloat16(v0); h01.x = h; l01.x = __float2bfloat16(v0 - __bfloat162float(h));
                h = __float2bfloat16(v1); h01.y = h; l01.y = __float2bfloat16(v1 - __bfloat162float(h));
                h = __float2bfloat16(v2); h23.x = h; l23.x = __float2bfloat16(v2 - __bfloat162float(h));
                h = __float2bfloat16(v3); h23.y = h; l23.y = __float2bfloat16(v3 - __bfloat162float(h));
                *(__nv_bfloat162*)(Ch + (size_t)r0 * ldc + c)       = h01;
                *(__nv_bfloat162*)(Cl + (size_t)r0 * ldc + c)       = l01;
                *(__nv_bfloat162*)(Ch + (size_t)(r0 + 8) * ldc + c) = h23;
                *(__nv_bfloat162*)(Cl + (size_t)(r0 + 8) * ldc + c) = l23;
            } else {
                *(float2*)(Cf + (size_t)r0 * ldc + c)       = make_float2(v0, v1);
                *(float2*)(Cf + (size_t)(r0 + 8) * ldc + c) = make_float2(v2, v3);
            }
        }
    }
}

// ================= merged weight prep =================
struct PrepArgs {
    const float* W[8];
    const float* b4[2];
    __nv_bfloat16* H[8];
    __nv_bfloat16* L[8];
    float* bp[2];
};

#define PREP_TOTAL 1900544

__global__ void prep_all(PrepArgs a)
{
    int idx = blockIdx.x * 256 + threadIdx.x;
    if (idx >= PREP_TOTAL) return;
    int c = 0, off = idx;
    if (off >= 950272) { c = 1; off -= 950272; }
    int seg, K, N, Kpad;
    if (off < 32768)       { seg = 0; K = 32;  N = 512; Kpad = 64;  }
    else if (off < 294912) { seg = 1; off -= 32768;  K = 512; N = 512; Kpad = 512; }
    else if (off < 557056) { seg = 2; off -= 294912; K = 512; N = 512; Kpad = 512; }
    else                   { seg = 3; off -= 557056; K = 512; N = 736; Kpad = 512; }
    const int widx = c * 4 + seg;
    const int n = off / Kpad, k = off - n * Kpad;
    float v = (k < K && n < N) ? a.W[widx][(size_t)k * N + n] : 0.f;
    __nv_bfloat16 h = __float2bfloat16(v);
    a.H[widx][off] = h;
    a.L[widx][off] = __float2bfloat16(v - __bfloat162float(h));
    if (seg == 3 && k == 0) a.bp[c][n] = (n < N) ? a.b4[c][n] : 0.f;
}

__global__ void split_x(const float* __restrict__ x,
                        __nv_bfloat16* __restrict__ H, __nv_bfloat16* __restrict__ L)
{
    int idx = blockIdx.x * 256 + threadIdx.x;
    int s = idx >> 6, d = idx & 63;
    float v = (d < HALF) ? x[(size_t)s * 64 + d] : 0.f;
    __nv_bfloat16 h = __float2bfloat16(v);
    H[idx] = h;
    L[idx] = __float2bfloat16(v - __bfloat162float(h));
}

// ================= spline =================
__device__ __forceinline__ float softplusf(float x) {
    return (x > 0.f) ? (x + log1pf(expf(-x))) : log1pf(expf(x));
}

__global__ void __launch_bounds__(256) spline_kernel(
    const float* __restrict__ y, int ldy,
    const float* __restrict__ cond,
    float* __restrict__ out_y, int ldo,
    float* __restrict__ logdet, int add,
    __nv_bfloat16* __restrict__ upH, __nv_bfloat16* __restrict__ upL)
{
    const int gid = blockIdx.x * 256 + threadIdx.x;
    const int s   = gid >> 5;
    const int dim = gid & 31;
    if (s >= NS) return;

    const float* p = cond + (size_t)s * NOUTP + dim * 23;
    const float x = y[(size_t)s * ldy + dim];

    float rw[KB], rh[KB];
#pragma unroll
    for (int i = 0; i < KB; i++) rw[i] = p[i];
#pragma unroll
    for (int i = 0; i < KB; i++) rh[i] = p[KB + i];

    float cw[KB + 1], wid[KB];
    {
        float m = rw[0];
#pragma unroll
        for (int i = 1; i < KB; i++) m = fmaxf(m, rw[i]);
        float s1 = 0.f, e[KB];
#pragma unroll
        for (int i = 0; i < KB; i++) { e[i] = expf(rw[i] - m); s1 += e[i]; }
        float inv1 = 1.f / s1, Wv[KB];
#pragma unroll
        for (int i = 0; i < KB; i++) Wv[i] = 2.f * TB * e[i] * inv1;
        float m2 = Wv[0];
#pragma unroll
        for (int i = 1; i < KB; i++) m2 = fmaxf(m2, Wv[i]);
        float s2 = 0.f;
#pragma unroll
        for (int i = 0; i < KB; i++) { e[i] = expf(Wv[i] - m2); s2 += e[i]; }
        float inv2 = 1.f / s2;
        float run = 0.f;
        cw[0] = -TB;
#pragma unroll
        for (int i = 0; i < KB; i++) {
            float w = 0.001f + (1.f - 0.001f * KB) * e[i] * inv2;
            run += w;
            cw[i + 1] = 2.f * TB * run - TB;
        }
        cw[KB] = TB;
#pragma unroll
        for (int i = 0; i < KB; i++) wid[i] = cw[i + 1] - cw[i];
    }

    float ch[KB + 1], hei[KB];
    {
        float m = rh[0];
#pragma unroll
        for (int i = 1; i < KB; i++) m = fmaxf(m, rh[i]);
        float s1 = 0.f, e[KB];
#pragma unroll
        for (int i = 0; i < KB; i++) { e[i] = expf(rh[i] - m); s1 += e[i]; }
        float inv1 = 1.f / s1, Hv[KB];
#pragma unroll
        for (int i = 0; i < KB; i++) Hv[i] = 2.f * TB * e[i] * inv1;
        float m2 = Hv[0];
#pragma unroll
        for (int i = 1; i < KB; i++) m2 = fmaxf(m2, Hv[i]);
        float s2 = 0.f;
#pragma unroll
        for (int i = 0; i < KB; i++) { e[i] = expf(Hv[i] - m2); s2 += e[i]; }
        float inv2 = 1.f / s2;
        float run = 0.f;
        ch[0] = -TB;
#pragma unroll
        for (int i = 0; i < KB; i++) {
            float h = 0.001f + (1.f - 0.001f * KB) * e[i] * inv2;
            run += h;
            ch[i + 1] = 2.f * TB * run - TB;
        }
        ch[KB] = TB;
#pragma unroll
        for (int i = 0; i < KB; i++) hei[i] = ch[i + 1] - ch[i];
    }

    float der[KB + 1];
    {
        const float CONST = 0.5397432446f;
        der[0] = 0.001f + softplusf(CONST);
        der[KB] = der[0];
#pragma unroll
        for (int i = 0; i < KB - 1; i++)
            der[i + 1] = 0.001f + softplusf(softplusf(p[2 * KB + i]));
    }

    const bool inside = (x >= -TB) && (x <= TB);
    const float xc = fminf(fmaxf(x, -TB), TB);
    int cnt = 0;
#pragma unroll
    for (int j = 0; j <= KB; j++) {
        float ce = cw[j] + ((j == KB) ? 1e-6f : 0.f);
        cnt += (xc >= ce) ? 1 : 0;
    }
    int idx = min(max(cnt - 1, 0), KB - 1);

    float in_cw = 0.f, in_w = 1.f, in_ch = 0.f, in_h = 1.f, in_der = 1.f, in_der1 = 1.f;
#pragma unroll
    for (int j = 0; j < KB; j++) {
        if (j == idx) {
            in_cw = cw[j]; in_w = wid[j]; in_ch = ch[j]; in_h = hei[j];
            in_der = der[j]; in_der1 = der[j + 1];
        }
    }
    const float in_d = in_h / in_w;
    const float theta = (xc - in_cw) / in_w;
    const float t1mt  = theta * (1.f - theta);
    const float num   = in_h * (in_d * theta * theta + in_der * t1mt);
    const float den   = in_d + (in_der + in_der1 - 2.f * in_d) * t1mt;
    const float outv  = in_ch + num / den;
    const float omt   = 1.f - theta;
    const float dnum  = in_d * in_d * (in_der1 * theta * theta + 2.f * in_d * t1mt + in_der * omt * omt);
    float lad = logf(dnum) - 2.f * logf(den);

    const float fv = inside ? outv : x;
    out_y[(size_t)s * ldo + dim] = fv;
    lad = inside ? lad : 0.f;

    if (upH) {
        __nv_bfloat16 h = __float2bfloat16(fv);
        float rem = fv - __bfloat162float(h);
        upH[(size_t)s * 64 + dim] = h;
        upL[(size_t)s * 64 + dim] = __float2bfloat16(rem);
        upH[(size_t)s * 64 + 32 + dim] = __float2bfloat16(0.f);
        upL[(size_t)s * 64 + 32 + dim] = __float2bfloat16(0.f);
    }

#pragma unroll
    for (int off = 16; off > 0; off >>= 1)
        lad += __shfl_down_sync(0xffffffffu, lad, off);
    if (dim == 0) {
        if (add) logdet[s] += lad;
        else     logdet[s]  = lad;
    }
}

// ================= launch =================
extern "C" void kernel_launch(void* const* d_in, const int* in_sizes, int n_in,
                              void* d_out, int out_size)
{
    const float* x = (const float*)d_in[0];
    const float* w[2][4] = {{(const float*)d_in[1], (const float*)d_in[3], (const float*)d_in[5], (const float*)d_in[7]},
                            {(const float*)d_in[9], (const float*)d_in[11], (const float*)d_in[13], (const float*)d_in[15]}};
    const float* bb[2][4] = {{(const float*)d_in[2], (const float*)d_in[4], (const float*)d_in[6], (const float*)d_in[8]},
                             {(const float*)d_in[10], (const float*)d_in[12], (const float*)d_in[14], (const float*)d_in[16]}};

    float* out    = (float*)d_out;
    float* logdet = out + (size_t)NS * 64;

    __nv_bfloat16 *xH, *xL, *aH0, *aL0, *aH1, *aL1;
    __nv_bfloat16 *w1H, *w1L, *w2H, *w2L, *w3H, *w3L, *w4H, *w4L;
    float *bufC, *b4p;
    cudaGetSymbolAddress((void**)&xH, g_xH);   cudaGetSymbolAddress((void**)&xL, g_xL);
    cudaGetSymbolAddress((void**)&aH0, g_aH0); cudaGetSymbolAddress((void**)&aL0, g_aL0);
    cudaGetSymbolAddress((void**)&aH1, g_aH1); cudaGetSymbolAddress((void**)&aL1, g_aL1);
    cudaGetSymbolAddress((void**)&w1H, g_w1H); cudaGetSymbolAddress((void**)&w1L, g_w1L);
    cudaGetSymbolAddress((void**)&w2H, g_w2H); cudaGetSymbolAddress((void**)&w2L, g_w2L);
    cudaGetSymbolAddress((void**)&w3H, g_w3H); cudaGetSymbolAddress((void**)&w3L, g_w3L);
    cudaGetSymbolAddress((void**)&w4H, g_w4H); cudaGetSymbolAddress((void**)&w4L, g_w4L);
    cudaGetSymbolAddress((void**)&bufC, g_bufC);
    cudaGetSymbolAddress((void**)&b4p, g_b4p);

    cudaFuncSetAttribute(gemm_bf16x2<2,1,1>, cudaFuncAttributeMaxDynamicSharedMemorySize, SMEM_TOTAL);
    cudaFuncSetAttribute(gemm_bf16x2<16,1,1>, cudaFuncAttributeMaxDynamicSharedMemorySize, SMEM_TOTAL);
    cudaFuncSetAttribute(gemm_bf16x2<16,0,0>, cudaFuncAttributeMaxDynamicSharedMemorySize, SMEM_TOTAL);

    PrepArgs pa;
    for (int c = 0; c < 2; c++) {
        for (int s = 0; s < 4; s++) pa.W[c*4 + s] = w[c][s];
        pa.b4[c] = bb[c][3];
        pa.H[c*4 + 0] = w1H + c*512*64;  pa.L[c*4 + 0] = w1L + c*512*64;
        pa.H[c*4 + 1] = w2H + c*512*512; pa.L[c*4 + 1] = w2L + c*512*512;
        pa.H[c*4 + 2] = w3H + c*512*512; pa.L[c*4 + 2] = w3L + c*512*512;
        pa.H[c*4 + 3] = w4H + c*768*512; pa.L[c*4 + 3] = w4L + c*768*512;
        pa.bp[c] = b4p + c*NOUTP;
    }
    prep_all<<<(PREP_TOTAL + 255)/256, 256>>>(pa);
    split_x<<<(NS*64)/256, 256>>>(x, xH, xL);

    const dim3 gemmBlk(NTHR);                       // 128 threads — GEMM only
    const dim3 g512(NHID / BN, NS / BM);            // (4, 512)
    const dim3 g768(NOUTP / BN, NS / BM);           // (6, 512)
    const dim3 splineBlk(256);                      // spline indexing assumes 256!
    const int splineBlocks = (NS * 32) / 256;

    for (int c = 0; c < 2; c++) {
        gemm_bf16x2<2,1,1><<<g512, gemmBlk, SMEM_TOTAL>>>(xH, xL, 64,
            w1H + c*512*64, w1L + c*512*64, bb[c][0], aH0, aL0, nullptr, NHID);
        gemm_bf16x2<16,1,1><<<g512, gemmBlk, SMEM_TOTAL>>>(aH0, aL0, NHID,
            w2H + c*512*512, w2L + c*512*512, bb[c][1], aH1, aL1, nullptr, NHID);
        gemm_bf16x2<16,1,1><<<g512, gemmBlk, SMEM_TOTAL>>>(aH1, aL1, NHID,
            w3H + c*512*512, w3L + c*512*512, bb[c][2], aH0, aL0, nullptr, NHID);
        gemm_bf16x2<16,0,0><<<g768, gemmBlk, SMEM_TOTAL>>>(aH0, aL0, NHID,
            w4H + c*768*512, w4L + c*768*512, b4p + c*NOUTP, nullptr, nullptr, bufC, NOUTP);
        if (c == 0)
            spline_kernel<<<splineBlocks, splineBlk>>>(x + HALF, 64, bufC, out + HALF, 64, logdet, 0, xH, xL);
        else
            spline_kernel<<<splineBlocks, splineBlk>>>(x, 64, bufC, out, 64, logdet, 1, nullptr, nullptr);
    }
}

// round 10
// speedup vs baseline: 1.0860x; 1.0035x over previous
#include <cuda_runtime.h>
#include <cuda_bf16.h>
#include <cstdint>

#define NS      65536
#define HALF    32
#define NHID    512
#define NOUT    736
#define NOUTP   768
#define KB      8
#define TB      3.0f

#define BM      128
#define BN      64
#define BKE     32
#define NTHR    128

// stage: A 128 rows x 128B (hi|lo packed) = 16KB, B 64 rows x 128B = 8KB => 24KB; 3 stages
#define SA      0
#define SB      16384
#define STAGE   24576
#define SMEM_TOTAL (3*STAGE)   // 72KB -> 3 CTAs/SM

// ================= static scratch =================
__device__ __nv_bfloat16 g_xH[(size_t)NS*64];
__device__ __nv_bfloat16 g_xL[(size_t)NS*64];
__device__ __nv_bfloat16 g_aH0[(size_t)NS*NHID];
__device__ __nv_bfloat16 g_aL0[(size_t)NS*NHID];
__device__ __nv_bfloat16 g_aH1[(size_t)NS*NHID];
__device__ __nv_bfloat16 g_aL1[(size_t)NS*NHID];
__device__ float         g_bufC[(size_t)NS*NOUTP];
__device__ __nv_bfloat16 g_w1H[2][512*64],  g_w1L[2][512*64];
__device__ __nv_bfloat16 g_w2H[2][512*512], g_w2L[2][512*512];
__device__ __nv_bfloat16 g_w3H[2][512*512], g_w3L[2][512*512];
__device__ __nv_bfloat16 g_w4H[2][768*512], g_w4L[2][768*512];
__device__ float         g_b4p[2][NOUTP];

// ================= helpers =================
__device__ __forceinline__ uint32_t smem_u32(const void* p) {
    uint32_t a;
    asm("{ .reg .u64 t; cvta.to.shared.u64 t, %1; cvt.u32.u64 %0, t; }" : "=r"(a) : "l"(p));
    return a;
}
#define SWZ(x) ((x) ^ (((x) >> 3) & 0x70))

#define CP16(dst, src) asm volatile("cp.async.cg.shared.global [%0], [%1], 16;" :: "r"(dst), "l"(src))
#define CP_COMMIT()    asm volatile("cp.async.commit_group;" ::: "memory")
#define CP_WAIT(N)     asm volatile("cp.async.wait_group %0;" :: "n"(N) : "memory")

#define LDSM4(r, a) \
    asm volatile("ldmatrix.sync.aligned.m8n8.x4.shared.b16 {%0,%1,%2,%3}, [%4];" \
        : "=r"((r)[0]), "=r"((r)[1]), "=r"((r)[2]), "=r"((r)[3]) : "r"(a))

#define MMA16816(c, a, b0, b1) \
    asm volatile("mma.sync.aligned.m16n8k16.row.col.f32.bf16.bf16.f32 " \
        "{%0,%1,%2,%3}, {%4,%5,%6,%7}, {%8,%9}, {%0,%1,%2,%3};" \
        : "+f"((c)[0]), "+f"((c)[1]), "+f"((c)[2]), "+f"((c)[3]) \
        : "r"((a)[0]), "r"((a)[1]), "r"((a)[2]), "r"((a)[3]), "r"(b0), "r"(b1))

// ================= GEMM =================
// C[M,N'] = act(A[M,K'] @ B[N',K']^T + bias); split bf16x2 operands, 3-term HMMA.
// 128x64 tile, 4 warps (2x2, 64x32 each), BKE=32 packed hi|lo, 3-stage ring, 3 CTAs/SM.
template <int KT, int ACT, int SPLIT>
__global__ void __launch_bounds__(NTHR, 3) gemm_bf16x2(
    const __nv_bfloat16* __restrict__ Ah, const __nv_bfloat16* __restrict__ Al, int lda,
    const __nv_bfloat16* __restrict__ Bh, const __nv_bfloat16* __restrict__ Bl,
    const float* __restrict__ bias,
    __nv_bfloat16* __restrict__ Ch, __nv_bfloat16* __restrict__ Cl,
    float* __restrict__ Cf, int ldc)
{
    extern __shared__ __align__(1024) char smem[];
    const uint32_t sb = smem_u32(smem);
    const int tid  = threadIdx.x;
    const int wid  = tid >> 5;
    const int l    = tid & 31;
    const int wm   = wid & 1;          // 2 warps over M -> 64 rows
    const int wn   = wid >> 1;         // 2 warps over N -> 32 cols
    const int row0 = blockIdx.y * BM;
    const int col0 = blockIdx.x * BN;
    const int ldb  = KT * BKE;

    float acc[4][4][4];
#pragma unroll
    for (int i = 0; i < 4; i++)
#pragma unroll
        for (int j = 0; j < 4; j++)
#pragma unroll
            for (int q = 0; q < 4; q++) acc[i][j][q] = 0.f;

    // tile loader: rows = [hi(4x16B) | lo(4x16B)]; A 128 rows, B 64 rows
    auto load_tile = [&](int s, int m) {
        const uint32_t sbase = sb + s * STAGE;
        const int koff = m * BKE;
#pragma unroll
        for (int i = 0; i < 4; i++) {            // A: 512 (r,q) pairs
            int c = tid + i * NTHR;
            int r = c >> 2, q = c & 3;
            uint32_t offH = SWZ(r * 128 + q * 16);
            uint32_t offL = SWZ(r * 128 + 64 + q * 16);
            const size_t ga = (size_t)(row0 + r) * lda + koff + q * 8;
            CP16(sbase + SA + offH, Ah + ga);
            CP16(sbase + SA + offL, Al + ga);
        }
#pragma unroll
        for (int i = 0; i < 2; i++) {            // B: 256 (n,q) pairs
            int c = tid + i * NTHR;
            int n = c >> 2, q = c & 3;
            uint32_t offH = SWZ(n * 128 + q * 16);
            uint32_t offL = SWZ(n * 128 + 64 + q * 16);
            const size_t gb = (size_t)(col0 + n) * ldb + koff + q * 8;
            CP16(sbase + SB + offH, Bh + gb);
            CP16(sbase + SB + offL, Bl + gb);
        }
    };

    auto compute = [&](int s) {
        const uint32_t AB = sb + s * STAGE + SA;
        const uint32_t BB = sb + s * STAGE + SB;
#pragma unroll
        for (int ks = 0; ks < 2; ks++) {
            uint32_t ah[4][4], al[4][4], bh[2][4], bl[2][4];
#pragma unroll
            for (int j16 = 0; j16 < 2; j16++) {
                int n = wn * 32 + j16 * 16 + (l & 7) + ((l >> 4) << 3);
                int colb = ks * 32 + ((l >> 3) & 1) * 16;
                uint32_t sw = (uint32_t)((n & 7) << 4);
                LDSM4(bh[j16], BB + n * 128 + (colb ^ sw));
                LDSM4(bl[j16], BB + n * 128 + ((64 + colb) ^ sw));
            }
#pragma unroll
            for (int i = 0; i < 4; i++) {
                int row = wm * 64 + i * 16 + (l & 15);
                int colb = ks * 32 + (l >> 4) * 16;
                uint32_t sw = (uint32_t)((row & 7) << 4);
                LDSM4(ah[i], AB + row * 128 + (colb ^ sw));
                LDSM4(al[i], AB + row * 128 + ((64 + colb) ^ sw));
            }
            // term-major: 16 hh, 16 hl, 16 lh
#pragma unroll
            for (int i = 0; i < 4; i++)
#pragma unroll
                for (int j16 = 0; j16 < 2; j16++)
#pragma unroll
                    for (int hf = 0; hf < 2; hf++)
                        MMA16816(acc[i][j16 * 2 + hf], ah[i], bh[j16][hf*2], bh[j16][hf*2+1]);
#pragma unroll
            for (int i = 0; i < 4; i++)
#pragma unroll
                for (int j16 = 0; j16 < 2; j16++)
#pragma unroll
                    for (int hf = 0; hf < 2; hf++)
                        MMA16816(acc[i][j16 * 2 + hf], ah[i], bl[j16][hf*2], bl[j16][hf*2+1]);
#pragma unroll
            for (int i = 0; i < 4; i++)
#pragma unroll
                for (int j16 = 0; j16 < 2; j16++)
#pragma unroll
                    for (int hf = 0; hf < 2; hf++)
                        MMA16816(acc[i][j16 * 2 + hf], al[i], bh[j16][hf*2], bh[j16][hf*2+1]);
        }
    };

    // 3-stage pipeline
    load_tile(0, 0); CP_COMMIT();
    if (KT > 1) { load_tile(1, 1); CP_COMMIT(); }
#pragma unroll
    for (int kt = 0; kt < KT; kt++) {
        if (kt < KT - 1) CP_WAIT(1); else CP_WAIT(0);
        __syncthreads();
        if (kt + 2 < KT) { load_tile((kt + 2) % 3, kt + 2); CP_COMMIT(); }
        compute(kt % 3);
    }

    // ---- epilogue ----
#pragma unroll
    for (int i = 0; i < 4; i++) {
        const int r0 = row0 + wm * 64 + i * 16 + (l >> 2);
#pragma unroll
        for (int j = 0; j < 4; j++) {
            const int c = col0 + wn * 32 + j * 8 + (l & 3) * 2;
            const float b0 = bias[c], b1 = bias[c + 1];
            float v0 = acc[i][j][0] + b0, v1 = acc[i][j][1] + b1;
            float v2 = acc[i][j][2] + b0, v3 = acc[i][j][3] + b1;
            if (ACT) {
                v0 = (v0 > 0.f) ? v0 : 0.2f * v0;
                v1 = (v1 > 0.f) ? v1 : 0.2f * v1;
                v2 = (v2 > 0.f) ? v2 : 0.2f * v2;
                v3 = (v3 > 0.f) ? v3 : 0.2f * v3;
            }
            if (SPLIT) {
                __nv_bfloat162 h01, h23, l01, l23;
                __nv_bfloat16 h;
                h = __float2bfloat16(v0); h01.x = h; l01.x = __float2bfloat16(v0 - __bfloat162float(h));
                h = __float2bfloat16(v1); h01.y = h; l01.y = __float2bfloat16(v1 - __bfloat162float(h));
                h = __float2bfloat16(v2); h23.x = h; l23.x = __float2bfloat16(v2 - __bfloat162float(h));
                h = __float2bfloat16(v3); h23.y = h; l23.y = __float2bfloat16(v3 - __bfloat162float(h));
                *(__nv_bfloat162*)(Ch + (size_t)r0 * ldc + c)       = h01;
                *(__nv_bfloat162*)(Cl + (size_t)r0 * ldc + c)       = l01;
                *(__nv_bfloat162*)(Ch + (size_t)(r0 + 8) * ldc + c) = h23;
                *(__nv_bfloat162*)(Cl + (size_t)(r0 + 8) * ldc + c) = l23;
            } else {
                *(float2*)(Cf + (size_t)r0 * ldc + c)       = make_float2(v0, v1);
                *(float2*)(Cf + (size_t)(r0 + 8) * ldc + c) = make_float2(v2, v3);
            }
        }
    }
}

// ================= merged weight prep =================
struct PrepArgs {
    const float* W[8];
    const float* b4[2];
    __nv_bfloat16* H[8];
    __nv_bfloat16* L[8];
    float* bp[2];
};

#define PREP_TOTAL 1900544

__global__ void prep_all(PrepArgs a)
{
    int idx = blockIdx.x * 256 + threadIdx.x;
    if (idx >= PREP_TOTAL) return;
    int c = 0, off = idx;
    if (off >= 950272) { c = 1; off -= 950272; }
    int seg, K, N, Kpad;
    if (off < 32768)       { seg = 0; K = 32;  N = 512; Kpad = 64;  }
    else if (off < 294912) { seg = 1; off -= 32768;  K = 512; N = 512; Kpad = 512; }
    else if (off < 557056) { seg = 2; off -= 294912; K = 512; N = 512; Kpad = 512; }
    else                   { seg = 3; off -= 557056; K = 512; N = 736; Kpad = 512; }
    const int widx = c * 4 + seg;
    const int n = off / Kpad, k = off - n * Kpad;
    float v = (k < K && n < N) ? a.W[widx][(size_t)k * N + n] : 0.f;
    __nv_bfloat16 h = __float2bfloat16(v);
    a.H[widx][off] = h;
    a.L[widx][off] = __float2bfloat16(v - __bfloat162float(h));
    if (seg == 3 && k == 0) a.bp[c][n] = (n < N) ? a.b4[c][n] : 0.f;
}

__global__ void split_x(const float* __restrict__ x,
                        __nv_bfloat16* __restrict__ H, __nv_bfloat16* __restrict__ L)
{
    int idx = blockIdx.x * 256 + threadIdx.x;
    int s = idx >> 6, d = idx & 63;
    float v = (d < HALF) ? x[(size_t)s * 64 + d] : 0.f;
    __nv_bfloat16 h = __float2bfloat16(v);
    H[idx] = h;
    L[idx] = __float2bfloat16(v - __bfloat162float(h));
}

// ================= spline =================
__device__ __forceinline__ float softplusf(float x) {
    return (x > 0.f) ? (x + log1pf(expf(-x))) : log1pf(expf(x));
}

__global__ void __launch_bounds__(256) spline_kernel(
    const float* __restrict__ y, int ldy,
    const float* __restrict__ cond,
    float* __restrict__ out_y, int ldo,
    float* __restrict__ logdet, int add,
    __nv_bfloat16* __restrict__ upH, __nv_bfloat16* __restrict__ upL)
{
    const int gid = blockIdx.x * 256 + threadIdx.x;
    const int s   = gid >> 5;
    const int dim = gid & 31;
    if (s >= NS) return;

    const float* p = cond + (size_t)s * NOUTP + dim * 23;
    const float x = y[(size_t)s * ldy + dim];

    float rw[KB], rh[KB];
#pragma unroll
    for (int i = 0; i < KB; i++) rw[i] = p[i];
#pragma unroll
    for (int i = 0; i < KB; i++) rh[i] = p[KB + i];

    float cw[KB + 1], wid[KB];
    {
        float m = rw[0];
#pragma unroll
        for (int i = 1; i < KB; i++) m = fmaxf(m, rw[i]);
        float s1 = 0.f, e[KB];
#pragma unroll
        for (int i = 0; i < KB; i++) { e[i] = expf(rw[i] - m); s1 += e[i]; }
        float inv1 = 1.f / s1, Wv[KB];
#pragma unroll
        for (int i = 0; i < KB; i++) Wv[i] = 2.f * TB * e[i] * inv1;
        float m2 = Wv[0];
#pragma unroll
        for (int i = 1; i < KB; i++) m2 = fmaxf(m2, Wv[i]);
        float s2 = 0.f;
#pragma unroll
        for (int i = 0; i < KB; i++) { e[i] = expf(Wv[i] - m2); s2 += e[i]; }
        float inv2 = 1.f / s2;
        float run = 0.f;
        cw[0] = -TB;
#pragma unroll
        for (int i = 0; i < KB; i++) {
            float w = 0.001f + (1.f - 0.001f * KB) * e[i] * inv2;
            run += w;
            cw[i + 1] = 2.f * TB * run - TB;
        }
        cw[KB] = TB;
#pragma unroll
        for (int i = 0; i < KB; i++) wid[i] = cw[i + 1] - cw[i];
    }

    float ch[KB + 1], hei[KB];
    {
        float m = rh[0];
#pragma unroll
        for (int i = 1; i < KB; i++) m = fmaxf(m, rh[i]);
        float s1 = 0.f, e[KB];
#pragma unroll
        for (int i = 0; i < KB; i++) { e[i] = expf(rh[i] - m); s1 += e[i]; }
        float inv1 = 1.f / s1, Hv[KB];
#pragma unroll
        for (int i = 0; i < KB; i++) Hv[i] = 2.f * TB * e[i] * inv1;
        float m2 = Hv[0];
#pragma unroll
        for (int i = 1; i < KB; i++) m2 = fmaxf(m2, Hv[i]);
        float s2 = 0.f;
#pragma unroll
        for (int i = 0; i < KB; i++) { e[i] = expf(Hv[i] - m2); s2 += e[i]; }
        float inv2 = 1.f / s2;
        float run = 0.f;
        ch[0] = -TB;
#pragma unroll
        for (int i = 0; i < KB; i++) {
            float h = 0.001f + (1.f - 0.001f * KB) * e[i] * inv2;
            run += h;
            ch[i + 1] = 2.f * TB * run - TB;
        }
        ch[KB] = TB;
#pragma unroll
        for (int i = 0; i < KB; i++) hei[i] = ch[i + 1] - ch[i];
    }

    float der[KB + 1];
    {
        const float CONST = 0.5397432446f;
        der[0] = 0.001f + softplusf(CONST);
        der[KB] = der[0];
#pragma unroll
        for (int i = 0; i < KB - 1; i++)
            der[i + 1] = 0.001f + softplusf(softplusf(p[2 * KB + i]));
    }

    const bool inside = (x >= -TB) && (x <= TB);
    const float xc = fminf(fmaxf(x, -TB), TB);
    int cnt = 0;
#pragma unroll
    for (int j = 0; j <= KB; j++) {
        float ce = cw[j] + ((j == KB) ? 1e-6f : 0.f);
        cnt += (xc >= ce) ? 1 : 0;
    }
    int idx = min(max(cnt - 1, 0), KB - 1);

    float in_cw = 0.f, in_w = 1.f, in_ch = 0.f, in_h = 1.f, in_der = 1.f, in_der1 = 1.f;
#pragma unroll
    for (int j = 0; j < KB; j++) {
        if (j == idx) {
            in_cw = cw[j]; in_w = wid[j]; in_ch = ch[j]; in_h = hei[j];
            in_der = der[j]; in_der1 = der[j + 1];
        }
    }
    const float in_d = in_h / in_w;
    const float theta = (xc - in_cw) / in_w;
    const float t1mt  = theta * (1.f - theta);
    const float num   = in_h * (in_d * theta * theta + in_der * t1mt);
    const float den   = in_d + (in_der + in_der1 - 2.f * in_d) * t1mt;
    const float outv  = in_ch + num / den;
    const float omt   = 1.f - theta;
    const float dnum  = in_d * in_d * (in_der1 * theta * theta + 2.f * in_d * t1mt + in_der * omt * omt);
    float lad = logf(dnum) - 2.f * logf(den);

    const float fv = inside ? outv : x;
    out_y[(size_t)s * ldo + dim] = fv;
    lad = inside ? lad : 0.f;

    if (upH) {
        __nv_bfloat16 h = __float2bfloat16(fv);
        float rem = fv - __bfloat162float(h);
        upH[(size_t)s * 64 + dim] = h;
        upL[(size_t)s * 64 + dim] = __float2bfloat16(rem);
        upH[(size_t)s * 64 + 32 + dim] = __float2bfloat16(0.f);
        upL[(size_t)s * 64 + 32 + dim] = __float2bfloat16(0.f);
    }

#pragma unroll
    for (int off = 16; off > 0; off >>= 1)
        lad += __shfl_down_sync(0xffffffffu, lad, off);
    if (dim == 0) {
        if (add) logdet[s] += lad;
        else     logdet[s]  = lad;
    }
}

// ================= launch =================
extern "C" void kernel_launch(void* const* d_in, const int* in_sizes, int n_in,
                              void* d_out, int out_size)
{
    const float* x = (const float*)d_in[0];
    const float* w[2][4] = {{(const float*)d_in[1], (const float*)d_in[3], (const float*)d_in[5], (const float*)d_in[7]},
                            {(const float*)d_in[9], (const float*)d_in[11], (const float*)d_in[13], (const float*)d_in[15]}};
    const float* bb[2][4] = {{(const float*)d_in[2], (const float*)d_in[4], (const float*)d_in[6], (const float*)d_in[8]},
                             {(const float*)d_in[10], (const float*)d_in[12], (const float*)d_in[14], (const float*)d_in[16]}};

    float* out    = (float*)d_out;
    float* logdet = out + (size_t)NS * 64;

    __nv_bfloat16 *xH, *xL, *aH0, *aL0, *aH1, *aL1;
    __nv_bfloat16 *w1H, *w1L, *w2H, *w2L, *w3H, *w3L, *w4H, *w4L;
    float *bufC, *b4p;
    cudaGetSymbolAddress((void**)&xH, g_xH);   cudaGetSymbolAddress((void**)&xL, g_xL);
    cudaGetSymbolAddress((void**)&aH0, g_aH0); cudaGetSymbolAddress((void**)&aL0, g_aL0);
    cudaGetSymbolAddress((void**)&aH1, g_aH1); cudaGetSymbolAddress((void**)&aL1, g_aL1);
    cudaGetSymbolAddress((void**)&w1H, g_w1H); cudaGetSymbolAddress((void**)&w1L, g_w1L);
    cudaGetSymbolAddress((void**)&w2H, g_w2H); cudaGetSymbolAddress((void**)&w2L, g_w2L);
    cudaGetSymbolAddress((void**)&w3H, g_w3H); cudaGetSymbolAddress((void**)&w3L, g_w3L);
    cudaGetSymbolAddress((void**)&w4H, g_w4H); cudaGetSymbolAddress((void**)&w4L, g_w4L);
    cudaGetSymbolAddress((void**)&bufC, g_bufC);
    cudaGetSymbolAddress((void**)&b4p, g_b4p);

    cudaFuncSetAttribute(gemm_bf16x2<2,1,1>, cudaFuncAttributeMaxDynamicSharedMemorySize, SMEM_TOTAL);
    cudaFuncSetAttribute(gemm_bf16x2<16,1,1>, cudaFuncAttributeMaxDynamicSharedMemorySize, SMEM_TOTAL);
    cudaFuncSetAttribute(gemm_bf16x2<16,0,0>, cudaFuncAttributeMaxDynamicSharedMemorySize, SMEM_TOTAL);

    PrepArgs pa;
    for (int c = 0; c < 2; c++) {
        for (int s = 0; s < 4; s++) pa.W[c*4 + s] = w[c][s];
        pa.b4[c] = bb[c][3];
        pa.H[c*4 + 0] = w1H + c*512*64;  pa.L[c*4 + 0] = w1L + c*512*64;
        pa.H[c*4 + 1] = w2H + c*512*512; pa.L[c*4 + 1] = w2L + c*512*512;
        pa.H[c*4 + 2] = w3H + c*512*512; pa.L[c*4 + 2] = w3L + c*512*512;
        pa.H[c*4 + 3] = w4H + c*768*512; pa.L[c*4 + 3] = w4L + c*768*512;
        pa.bp[c] = b4p + c*NOUTP;
    }
    prep_all<<<(PREP_TOTAL + 255)/256, 256>>>(pa);
    split_x<<<(NS*64)/256, 256>>>(x, xH, xL);

    const dim3 gemmBlk(NTHR);
    const dim3 g512(NHID / BN, NS / BM);            // (8, 512)
    const dim3 g768(NOUTP / BN, NS / BM);           // (12, 512)
    const dim3 splineBlk(256);
    const int splineBlocks = (NS * 32) / 256;

    for (int c = 0; c < 2; c++) {
        gemm_bf16x2<2,1,1><<<g512, gemmBlk, SMEM_TOTAL>>>(xH, xL, 64,
            w1H + c*512*64, w1L + c*512*64, bb[c][0], aH0, aL0, nullptr, NHID);
        gemm_bf16x2<16,1,1><<<g512, gemmBlk, SMEM_TOTAL>>>(aH0, aL0, NHID,
            w2H + c*512*512, w2L + c*512*512, bb[c][1], aH1, aL1, nullptr, NHID);
        gemm_bf16x2<16,1,1><<<g512, gemmBlk, SMEM_TOTAL>>>(aH1, aL1, NHID,
            w3H + c*512*512, w3L + c*512*512, bb[c][2], aH0, aL0, nullptr, NHID);
        gemm_bf16x2<16,0,0><<<g768, gemmBlk, SMEM_TOTAL>>>(aH0, aL0, NHID,
            w4H + c*768*512, w4L + c*768*512, b4p + c*NOUTP, nullptr, nullptr, bufC, NOUTP);
        if (c == 0)
            spline_kernel<<<splineBlocks, splineBlk>>>(x + HALF, 64, bufC, out + HALF, 64, logdet, 0, xH, xL);
        else
            spline_kernel<<<splineBlocks, splineBlk>>>(x, 64, bufC, out, 64, logdet, 1, nullptr, nullptr);
    }
}

// round 12
// speedup vs baseline: 1.5600x; 1.4365x over previous
#include <cuda_runtime.h>
#include <cstdint>

#define NS      65536
#define HALF    32
#define NHID    512
#define NOUT    736
#define NOUTP   768
#define KB      8
#define TB      3.0f

#define BM      128
#define BN      64
#define BKB     128     // K elements (bytes) per tile
#define NTHR    128

// stage: Ah 128x128B=16K, Al 16K, Bh 64x128B=8K, Bl 8K => 48KB; 2 stages = 96KB -> 2 CTAs/SM
#define SAH     0
#define SAL     16384
#define SBH     32768
#define SBL     40960
#define STAGE   49152
#define SMEM_TOTAL (2*STAGE)

// ================= static scratch =================
__device__ int8_t g_xq1h[(size_t)NS*128], g_xq1l[(size_t)NS*128];
__device__ float  g_xs1[NS];
__device__ int8_t g_xq2h[(size_t)NS*128], g_xq2l[(size_t)NS*128];
__device__ float  g_xs2[NS];
__device__ int8_t g_q0h[(size_t)NS*512],  g_q0l[(size_t)NS*512];
__device__ float  g_s0[NS];
__device__ float  g_act[(size_t)NS*512];
__device__ float  g_bufC[(size_t)NS*NOUTP];
__device__ int8_t g_w1h[2][512*128], g_w1l[2][512*128];
__device__ int8_t g_w2h[2][512*512], g_w2l[2][512*512];
__device__ int8_t g_w3h[2][512*512], g_w3l[2][512*512];
__device__ int8_t g_w4h[2][768*512], g_w4l[2][768*512];
__device__ float  g_ws1[2][512], g_ws2[2][512], g_ws3[2][512], g_ws4[2][768];
__device__ float  g_b4p[2][768];

// ================= helpers =================
__device__ __forceinline__ uint32_t smem_u32(const void* p) {
    uint32_t a;
    asm("{ .reg .u64 t; cvta.to.shared.u64 t, %1; cvt.u32.u64 %0, t; }" : "=r"(a) : "l"(p));
    return a;
}
#define SWZ(x) ((x) ^ (((x) >> 3) & 0x70))

#define CP16(dst, src) asm volatile("cp.async.cg.shared.global [%0], [%1], 16;" :: "r"(dst), "l"(src))
#define CP_COMMIT()    asm volatile("cp.async.commit_group;" ::: "memory")
#define CP_WAIT(N)     asm volatile("cp.async.wait_group %0;" :: "n"(N) : "memory")

#define LDSM4(r, a) \
    asm volatile("ldmatrix.sync.aligned.m8n8.x4.shared.b16 {%0,%1,%2,%3}, [%4];" \
        : "=r"((r)[0]), "=r"((r)[1]), "=r"((r)[2]), "=r"((r)[3]) : "r"(a))

#define MMAI8(c, a, b0, b1) \
    asm volatile("mma.sync.aligned.m16n8k32.row.col.s32.s8.s8.s32 " \
        "{%0,%1,%2,%3}, {%4,%5,%6,%7}, {%8,%9}, {%0,%1,%2,%3};" \
        : "+r"((c)[0]), "+r"((c)[1]), "+r"((c)[2]), "+r"((c)[3]) \
        : "r"((a)[0]), "r"((a)[1]), "r"((a)[2]), "r"((a)[3]), "r"(b0), "r"(b1))

// ================= int8 split GEMM =================
// C[M,N] = act( sa[m]*sb[n]*(16384*ACC_hh + 128*ACC_mix) + bias[n] )
// 128x64 tile, 4 warps (2x2, 64x32 each), BKB=128, 2-stage, 2 CTAs/SM.
template <int KT, int ACT>
__global__ void __launch_bounds__(NTHR, 2) gemm_i8(
    const int8_t* __restrict__ Aq, const int8_t* __restrict__ Aql,
    const float* __restrict__ sA,
    const int8_t* __restrict__ Bq, const int8_t* __restrict__ Bql,
    const float* __restrict__ sB,
    const float* __restrict__ bias,
    float* __restrict__ C, int ldc)
{
    extern __shared__ __align__(1024) char smem[];
    const uint32_t sb_ = smem_u32(smem);
    const int tid  = threadIdx.x;
    const int wid  = tid >> 5;
    const int l    = tid & 31;
    const int wm   = wid & 1;
    const int wn   = wid >> 1;
    const int row0 = blockIdx.y * BM;
    const int col0 = blockIdx.x * BN;
    const int lda  = KT * BKB;

    int acc1[4][4][4], acc2[4][4][4];
#pragma unroll
    for (int i = 0; i < 4; i++)
#pragma unroll
        for (int j = 0; j < 4; j++)
#pragma unroll
            for (int q = 0; q < 4; q++) { acc1[i][j][q] = 0; acc2[i][j][q] = 0; }

    auto load_tile = [&](int s, int m) {
        const uint32_t sbase = sb_ + s * STAGE;
        const int koff = m * BKB;
#pragma unroll
        for (int i = 0; i < 8; i++) {           // A planes: 1024 16B-chunks each
            int c = tid + i * NTHR;
            int r = c >> 3, q = c & 7;
            uint32_t off = SWZ(r * 128 + q * 16);
            const size_t ga = (size_t)(row0 + r) * lda + koff + q * 16;
            CP16(sbase + SAH + off, Aq + ga);
            CP16(sbase + SAL + off, Aql + ga);
        }
#pragma unroll
        for (int i = 0; i < 4; i++) {           // B planes: 512 chunks each
            int c = tid + i * NTHR;
            int n = c >> 3, q = c & 7;
            uint32_t off = SWZ(n * 128 + q * 16);
            const size_t gb = (size_t)(col0 + n) * lda + koff + q * 16;
            CP16(sbase + SBH + off, Bq + gb);
            CP16(sbase + SBL + off, Bql + gb);
        }
    };

    auto compute = [&](int s) {
        const uint32_t AHB = sb_ + s * STAGE + SAH;
        const uint32_t ALB = sb_ + s * STAGE + SAL;
        const uint32_t BHB = sb_ + s * STAGE + SBH;
        const uint32_t BLB = sb_ + s * STAGE + SBL;
#pragma unroll
        for (int ksl = 0; ksl < 4; ksl++) {     // 4 x k32 slices per 128-byte tile
            uint32_t ah[4][4], al[4][4], bh[2][4], bl[2][4];
#pragma unroll
            for (int j16 = 0; j16 < 2; j16++) {
                int n = wn * 32 + j16 * 16 + (l & 7) + ((l >> 4) << 3);
                int colb = ksl * 32 + ((l >> 3) & 1) * 16;
                uint32_t sw = (uint32_t)((n & 7) << 4);
                LDSM4(bh[j16], BHB + n * 128 + (colb ^ sw));
                LDSM4(bl[j16], BLB + n * 128 + (colb ^ sw));
            }
#pragma unroll
            for (int i = 0; i < 4; i++) {
                int row = wm * 64 + i * 16 + (l & 15);
                int colb = ksl * 32 + (l >> 4) * 16;
                uint32_t sw = (uint32_t)((row & 7) << 4);
                LDSM4(ah[i], AHB + row * 128 + (colb ^ sw));
                LDSM4(al[i], ALB + row * 128 + (colb ^ sw));
            }
            // hh -> acc1 (16 indep MMAs)
#pragma unroll
            for (int i = 0; i < 4; i++)
#pragma unroll
                for (int j16 = 0; j16 < 2; j16++)
#pragma unroll
                    for (int hf = 0; hf < 2; hf++)
                        MMAI8(acc1[i][j16 * 2 + hf], ah[i], bh[j16][hf*2], bh[j16][hf*2+1]);
            // hl + lh -> acc2 (32 indep MMAs)
#pragma unroll
            for (int i = 0; i < 4; i++)
#pragma unroll
                for (int j16 = 0; j16 < 2; j16++)
#pragma unroll
                    for (int hf = 0; hf < 2; hf++)
                        MMAI8(acc2[i][j16 * 2 + hf], ah[i], bl[j16][hf*2], bl[j16][hf*2+1]);
#pragma unroll
            for (int i = 0; i < 4; i++)
#pragma unroll
                for (int j16 = 0; j16 < 2; j16++)
#pragma unroll
                    for (int hf = 0; hf < 2; hf++)
                        MMAI8(acc2[i][j16 * 2 + hf], al[i], bh[j16][hf*2], bh[j16][hf*2+1]);
        }
    };

    load_tile(0, 0); CP_COMMIT();
#pragma unroll
    for (int kt = 0; kt < KT; kt++) {
        CP_WAIT(0);
        __syncthreads();
        if (kt + 1 < KT) { load_tile((kt + 1) & 1, kt + 1); CP_COMMIT(); }
        compute(kt & 1);
    }

    // ---- epilogue ----
#pragma unroll
    for (int i = 0; i < 4; i++) {
        const int r0 = row0 + wm * 64 + i * 16 + (l >> 2);
        const float sa0 = sA[r0], sa1 = sA[r0 + 8];
#pragma unroll
        for (int j = 0; j < 4; j++) {
            const int c = col0 + wn * 32 + j * 8 + (l & 3) * 2;
            const float sb0 = sB[c], sb1 = sB[c + 1];
            const float b0 = bias[c], b1 = bias[c + 1];
            float f0 = fmaf((float)acc1[i][j][0], 16384.f, (float)acc2[i][j][0] * 128.f);
            float f1 = fmaf((float)acc1[i][j][1], 16384.f, (float)acc2[i][j][1] * 128.f);
            float f2 = fmaf((float)acc1[i][j][2], 16384.f, (float)acc2[i][j][2] * 128.f);
            float f3 = fmaf((float)acc1[i][j][3], 16384.f, (float)acc2[i][j][3] * 128.f);
            float v0 = fmaf(f0, sa0 * sb0, b0);
            float v1 = fmaf(f1, sa0 * sb1, b1);
            float v2 = fmaf(f2, sa1 * sb0, b0);
            float v3 = fmaf(f3, sa1 * sb1, b1);
            if (ACT) {
                v0 = (v0 > 0.f) ? v0 : 0.2f * v0;
                v1 = (v1 > 0.f) ? v1 : 0.2f * v1;
                v2 = (v2 > 0.f) ? v2 : 0.2f * v2;
                v3 = (v3 > 0.f) ? v3 : 0.2f * v3;
            }
            *(float2*)(C + (size_t)r0 * ldc + c)       = make_float2(v0, v1);
            *(float2*)(C + (size_t)(r0 + 8) * ldc + c) = make_float2(v2, v3);
        }
    }
}

// ================= activation quantization: warp per row =================
template <int NK>   // NK = kpad/32
__global__ void qact(const float* __restrict__ in, int inld, int ncols,
                     int8_t* __restrict__ qh, int8_t* __restrict__ ql,
                     float* __restrict__ scale)
{
    const int warp = (blockIdx.x * blockDim.x + threadIdx.x) >> 5;
    const int lane = threadIdx.x & 31;
    if (warp >= NS) return;
    const float* rp = in + (size_t)warp * inld;
    float vals[NK];
    float amax = 0.f;
#pragma unroll
    for (int i = 0; i < NK; i++) {
        int c = lane + 32 * i;
        float v = (c < ncols) ? rp[c] : 0.f;
        vals[i] = v;
        amax = fmaxf(amax, fabsf(v));
    }
#pragma unroll
    for (int off = 16; off > 0; off >>= 1)
        amax = fmaxf(amax, __shfl_xor_sync(0xffffffffu, amax, off));
    amax = fmaxf(amax, 1e-20f);
    const float sa    = amax * (1.f / 16256.f);
    const float inv   = 16256.f / amax;
    const float sa128 = sa * 128.f;
    const size_t base = (size_t)warp * (NK * 32);
#pragma unroll
    for (int i = 0; i < NK; i++) {
        int c = lane + 32 * i;
        float v = vals[i];
        int h = __float2int_rn(v * inv * (1.f / 128.f));
        float r = fmaf(-(float)h, sa128, v);
        int lo = __float2int_rn(r * inv);
        qh[base + c] = (int8_t)h;
        ql[base + c] = (int8_t)lo;
    }
    if (lane == 0) scale[warp] = sa;
}

// ================= weight quantization: warp per output col =================
struct QWArgs {
    const float* W[8];
    const float* b4[2];
    int8_t* H[8];
    int8_t* L8[8];
    float*  S[8];
    float*  bp[2];
};

__global__ void qweights(QWArgs a)
{
    const int gw   = (blockIdx.x * blockDim.x + threadIdx.x) >> 5;
    const int lane = threadIdx.x & 31;
    if (gw >= 4608) return;
    const int c   = (gw >= 2304) ? 1 : 0;
    int off = gw - c * 2304;
    int seg, n, K, N, Kpad;
    if (off < 512)       { seg = 0; n = off;        K = 32;  N = 512; Kpad = 128; }
    else if (off < 1024) { seg = 1; n = off - 512;  K = 512; N = 512; Kpad = 512; }
    else if (off < 1536) { seg = 2; n = off - 1024; K = 512; N = 512; Kpad = 512; }
    else                 { seg = 3; n = off - 1536; K = 512; N = 736; Kpad = 512; }
    const int widx = c * 4 + seg;
    const float* W = a.W[widx];
    const int nk = Kpad >> 5;   // 4 or 16

    float vals[16];
    float amax = 0.f;
#pragma unroll 16
    for (int i = 0; i < 16; i++) {
        if (i < nk) {
            int k = lane + 32 * i;
            float v = (k < K && n < N) ? W[(size_t)k * N + n] : 0.f;
            vals[i] = v;
            amax = fmaxf(amax, fabsf(v));
        }
    }
#pragma unroll
    for (int o = 16; o > 0; o >>= 1)
        amax = fmaxf(amax, __shfl_xor_sync(0xffffffffu, amax, o));
    amax = fmaxf(amax, 1e-20f);
    const float sbv   = amax * (1.f / 16256.f);
    const float inv   = 16256.f / amax;
    const float sb128 = sbv * 128.f;
    const size_t base = (size_t)n * Kpad;
#pragma unroll 16
    for (int i = 0; i < 16; i++) {
        if (i < nk) {
            int k = lane + 32 * i;
            float v = vals[i];
            int h = __float2int_rn(v * inv * (1.f / 128.f));
            float r = fmaf(-(float)h, sb128, v);
            int lo = __float2int_rn(r * inv);
            a.H[widx][base + k]  = (int8_t)h;
            a.L8[widx][base + k] = (int8_t)lo;
        }
    }
    if (lane == 0) {
        a.S[widx][n] = sbv;
        if (seg == 3) a.bp[c][n] = (n < 736) ? a.b4[c][n] : 0.f;
    }
}

// ================= spline =================
__device__ __forceinline__ float softplusf(float x) {
    return (x > 0.f) ? (x + log1pf(expf(-x))) : log1pf(expf(x));
}

__global__ void __launch_bounds__(256) spline_kernel(
    const float* __restrict__ y, int ldy,
    const float* __restrict__ cond,
    float* __restrict__ out_y, int ldo,
    float* __restrict__ logdet, int add,
    int8_t* __restrict__ qh, int8_t* __restrict__ ql, float* __restrict__ qs)
{
    const int gid = blockIdx.x * 256 + threadIdx.x;
    const int s   = gid >> 5;
    const int dim = gid & 31;
    if (s >= NS) return;

    const float* p = cond + (size_t)s * NOUTP + dim * 23;
    const float x = y[(size_t)s * ldy + dim];

    float rw[KB], rh[KB];
#pragma unroll
    for (int i = 0; i < KB; i++) rw[i] = p[i];
#pragma unroll
    for (int i = 0; i < KB; i++) rh[i] = p[KB + i];

    float cw[KB + 1], wid[KB];
    {
        float m = rw[0];
#pragma unroll
        for (int i = 1; i < KB; i++) m = fmaxf(m, rw[i]);
        float s1 = 0.f, e[KB];
#pragma unroll
        for (int i = 0; i < KB; i++) { e[i] = expf(rw[i] - m); s1 += e[i]; }
        float inv1 = 1.f / s1, Wv[KB];
#pragma unroll
        for (int i = 0; i < KB; i++) Wv[i] = 2.f * TB * e[i] * inv1;
        float m2 = Wv[0];
#pragma unroll
        for (int i = 1; i < KB; i++) m2 = fmaxf(m2, Wv[i]);
        float s2 = 0.f;
#pragma unroll
        for (int i = 0; i < KB; i++) { e[i] = expf(Wv[i] - m2); s2 += e[i]; }
        float inv2 = 1.f / s2;
        float run = 0.f;
        cw[0] = -TB;
#pragma unroll
        for (int i = 0; i < KB; i++) {
            float w = 0.001f + (1.f - 0.001f * KB) * e[i] * inv2;
            run += w;
            cw[i + 1] = 2.f * TB * run - TB;
        }
        cw[KB] = TB;
#pragma unroll
        for (int i = 0; i < KB; i++) wid[i] = cw[i + 1] - cw[i];
    }

    float ch[KB + 1], hei[KB];
    {
        float m = rh[0];
#pragma unroll
        for (int i = 1; i < KB; i++) m = fmaxf(m, rh[i]);
        float s1 = 0.f, e[KB];
#pragma unroll
        for (int i = 0; i < KB; i++) { e[i] = expf(rh[i] - m); s1 += e[i]; }
        float inv1 = 1.f / s1, Hv[KB];
#pragma unroll
        for (int i = 0; i < KB; i++) Hv[i] = 2.f * TB * e[i] * inv1;
        float m2 = Hv[0];
#pragma unroll
        for (int i = 1; i < KB; i++) m2 = fmaxf(m2, Hv[i]);
        float s2 = 0.f;
#pragma unroll
        for (int i = 0; i < KB; i++) { e[i] = expf(Hv[i] - m2); s2 += e[i]; }
        float inv2 = 1.f / s2;
        float run = 0.f;
        ch[0] = -TB;
#pragma unroll
        for (int i = 0; i < KB; i++) {
            float h = 0.001f + (1.f - 0.001f * KB) * e[i] * inv2;
            run += h;
            ch[i + 1] = 2.f * TB * run - TB;
        }
        ch[KB] = TB;
#pragma unroll
        for (int i = 0; i < KB; i++) hei[i] = ch[i + 1] - ch[i];
    }

    float der[KB + 1];
    {
        const float CONST = 0.5397432446f;
        der[0] = 0.001f + softplusf(CONST);
        der[KB] = der[0];
#pragma unroll
        for (int i = 0; i < KB - 1; i++)
            der[i + 1] = 0.001f + softplusf(softplusf(p[2 * KB + i]));
    }

    const bool inside = (x >= -TB) && (x <= TB);
    const float xc = fminf(fmaxf(x, -TB), TB);
    int cnt = 0;
#pragma unroll
    for (int j = 0; j <= KB; j++) {
        float ce = cw[j] + ((j == KB) ? 1e-6f : 0.f);
        cnt += (xc >= ce) ? 1 : 0;
    }
    int idx = min(max(cnt - 1, 0), KB - 1);

    float in_cw = 0.f, in_w = 1.f, in_ch = 0.f, in_h = 1.f, in_der = 1.f, in_der1 = 1.f;
#pragma unroll
    for (int j = 0; j < KB; j++) {
        if (j == idx) {
            in_cw = cw[j]; in_w = wid[j]; in_ch = ch[j]; in_h = hei[j];
            in_der = der[j]; in_der1 = der[j + 1];
        }
    }
    const float in_d = in_h / in_w;
    const float theta = (xc - in_cw) / in_w;
    const float t1mt  = theta * (1.f - theta);
    const float num   = in_h * (in_d * theta * theta + in_der * t1mt);
    const float den   = in_d + (in_der + in_der1 - 2.f * in_d) * t1mt;
    const float outv  = in_ch + num / den;
    const float omt   = 1.f - theta;
    const float dnum  = in_d * in_d * (in_der1 * theta * theta + 2.f * in_d * t1mt + in_der * omt * omt);
    float lad = logf(dnum) - 2.f * logf(den);

    const float fv = inside ? outv : x;
    out_y[(size_t)s * ldo + dim] = fv;
    lad = inside ? lad : 0.f;

    if (qh) {   // quantize row of 32 (padded to 128) for next coupling's layer-1
        float amax = fabsf(fv);
#pragma unroll
        for (int off = 16; off > 0; off >>= 1)
            amax = fmaxf(amax, __shfl_xor_sync(0xffffffffu, amax, off));
        amax = fmaxf(amax, 1e-20f);
        const float sa    = amax * (1.f / 16256.f);
        const float inv   = 16256.f / amax;
        const float sa128 = sa * 128.f;
        int h = __float2int_rn(fv * inv * (1.f / 128.f));
        float r = fmaf(-(float)h, sa128, fv);
        int lo = __float2int_rn(r * inv);
        const size_t base = (size_t)s * 128 + dim;
        qh[base] = (int8_t)h;  ql[base] = (int8_t)lo;
        qh[base + 32] = 0; ql[base + 32] = 0;
        qh[base + 64] = 0; ql[base + 64] = 0;
        qh[base + 96] = 0; ql[base + 96] = 0;
        if (dim == 0) qs[s] = sa;
    }

#pragma unroll
    for (int off = 16; off > 0; off >>= 1)
        lad += __shfl_down_sync(0xffffffffu, lad, off);
    if (dim == 0) {
        if (add) logdet[s] += lad;
        else     logdet[s]  = lad;
    }
}

// ================= launch =================
extern "C" void kernel_launch(void* const* d_in, const int* in_sizes, int n_in,
                              void* d_out, int out_size)
{
    const float* x = (const float*)d_in[0];
    const float* w[2][4] = {{(const float*)d_in[1], (const float*)d_in[3], (const float*)d_in[5], (const float*)d_in[7]},
                            {(const float*)d_in[9], (const float*)d_in[11], (const float*)d_in[13], (const float*)d_in[15]}};
    const float* bb[2][4] = {{(const float*)d_in[2], (const float*)d_in[4], (const float*)d_in[6], (const float*)d_in[8]},
                             {(const float*)d_in[10], (const float*)d_in[12], (const float*)d_in[14], (const float*)d_in[16]}};

    float* out    = (float*)d_out;
    float* logdet = out + (size_t)NS * 64;

    int8_t *xq1h, *xq1l, *xq2h, *xq2l, *q0h, *q0l;
    float  *xs1, *xs2, *s0, *actF, *bufC, *b4p;
    int8_t *w1h, *w1l, *w2h, *w2l, *w3h, *w3l, *w4h, *w4l;
    float  *ws1, *ws2, *ws3, *ws4;
    cudaGetSymbolAddress((void**)&xq1h, g_xq1h); cudaGetSymbolAddress((void**)&xq1l, g_xq1l);
    cudaGetSymbolAddress((void**)&xs1, g_xs1);
    cudaGetSymbolAddress((void**)&xq2h, g_xq2h); cudaGetSymbolAddress((void**)&xq2l, g_xq2l);
    cudaGetSymbolAddress((void**)&xs2, g_xs2);
    cudaGetSymbolAddress((void**)&q0h, g_q0h);   cudaGetSymbolAddress((void**)&q0l, g_q0l);
    cudaGetSymbolAddress((void**)&s0, g_s0);
    cudaGetSymbolAddress((void**)&actF, g_act);
    cudaGetSymbolAddress((void**)&bufC, g_bufC);
    cudaGetSymbolAddress((void**)&w1h, g_w1h); cudaGetSymbolAddress((void**)&w1l, g_w1l);
    cudaGetSymbolAddress((void**)&w2h, g_w2h); cudaGetSymbolAddress((void**)&w2l, g_w2l);
    cudaGetSymbolAddress((void**)&w3h, g_w3h); cudaGetSymbolAddress((void**)&w3l, g_w3l);
    cudaGetSymbolAddress((void**)&w4h, g_w4h); cudaGetSymbolAddress((void**)&w4l, g_w4l);
    cudaGetSymbolAddress((void**)&ws1, g_ws1); cudaGetSymbolAddress((void**)&ws2, g_ws2);
    cudaGetSymbolAddress((void**)&ws3, g_ws3); cudaGetSymbolAddress((void**)&ws4, g_ws4);
    cudaGetSymbolAddress((void**)&b4p, g_b4p);

    cudaFuncSetAttribute(gemm_i8<1,1>, cudaFuncAttributeMaxDynamicSharedMemorySize, SMEM_TOTAL);
    cudaFuncSetAttribute(gemm_i8<4,1>, cudaFuncAttributeMaxDynamicSharedMemorySize, SMEM_TOTAL);
    cudaFuncSetAttribute(gemm_i8<4,0>, cudaFuncAttributeMaxDynamicSharedMemorySize, SMEM_TOTAL);

    QWArgs qa;
    for (int c = 0; c < 2; c++) {
        for (int s = 0; s < 4; s++) qa.W[c*4 + s] = w[c][s];
        qa.b4[c] = bb[c][3];
        qa.H[c*4 + 0] = w1h + c*512*128; qa.L8[c*4 + 0] = w1l + c*512*128; qa.S[c*4 + 0] = ws1 + c*512;
        qa.H[c*4 + 1] = w2h + c*512*512; qa.L8[c*4 + 1] = w2l + c*512*512; qa.S[c*4 + 1] = ws2 + c*512;
        qa.H[c*4 + 2] = w3h + c*512*512; qa.L8[c*4 + 2] = w3l + c*512*512; qa.S[c*4 + 2] = ws3 + c*512;
        qa.H[c*4 + 3] = w4h + c*768*512; qa.L8[c*4 + 3] = w4l + c*768*512; qa.S[c*4 + 3] = ws4 + c*768;
        qa.bp[c] = b4p + c*768;
    }
    qweights<<<(4608 * 32 + 255) / 256, 256>>>(qa);
    // quantize lower half of x (layer-1 input for coupling 1), Kpad=128
    qact<4><<<NS / 8, 256>>>(x, 64, HALF, xq1h, xq1l, xs1);

    const dim3 gemmBlk(NTHR);
    const dim3 g512(NHID / BN, NS / BM);     // (8, 512)
    const dim3 g768(NOUTP / BN, NS / BM);    // (12, 512)
    const dim3 splineBlk(256);
    const int splineBlocks = (NS * 32) / 256;
    const int qactBlocks = NS / 8;

    for (int c = 0; c < 2; c++) {
        const int8_t* inH = (c == 0) ? xq1h : xq2h;
        const int8_t* inL = (c == 0) ? xq1l : xq2l;
        const float*  inS = (c == 0) ? xs1  : xs2;

        gemm_i8<1,1><<<g512, gemmBlk, SMEM_TOTAL>>>(inH, inL, inS,
            w1h + c*512*128, w1l + c*512*128, ws1 + c*512, bb[c][0], actF, NHID);
        qact<16><<<qactBlocks, 256>>>(actF, NHID, NHID, q0h, q0l, s0);

        gemm_i8<4,1><<<g512, gemmBlk, SMEM_TOTAL>>>(q0h, q0l, s0,
            w2h + c*512*512, w2l + c*512*512, ws2 + c*512, bb[c][1], actF, NHID);
        qact<16><<<qactBlocks, 256>>>(actF, NHID, NHID, q0h, q0l, s0);

        gemm_i8<4,1><<<g512, gemmBlk, SMEM_TOTAL>>>(q0h, q0l, s0,
            w3h + c*512*512, w3l + c*512*512, ws3 + c*512, bb[c][2], actF, NHID);
        qact<16><<<qactBlocks, 256>>>(actF, NHID, NHID, q0h, q0l, s0);

        gemm_i8<4,0><<<g768, gemmBlk, SMEM_TOTAL>>>(q0h, q0l, s0,
            w4h + c*768*512, w4l + c*768*512, ws4 + c*768, b4p + c*768, bufC, NOUTP);

        if (c == 0)
            spline_kernel<<<splineBlocks, splineBlk>>>(x + HALF, 64, bufC,
                out + HALF, 64, logdet, 0, xq2h, xq2l, xs2);
        else
            spline_kernel<<<splineBlocks, splineBlk>>>(x, 64, bufC,
                out, 64, logdet, 1, nullptr, nullptr, nullptr);
    }
}

// round 14
// speedup vs baseline: 1.5750x; 1.0096x over previous
#include <cuda_runtime.h>
#include <cstdint>

#define NS      65536
#define HALF    32
#define NHID    512
#define NOUT    736
#define NOUTP   768
#define KB      8
#define TB      3.0f

#define BM      128
#define BN      64
#define BKB     128
#define NTHR    128

#define SAH     0
#define SAL     16384
#define SBH     32768
#define SBL     40960
#define STAGE   49152
#define SMEM_TOTAL (2*STAGE)

// ================= static scratch =================
__device__ int8_t g_xq1h[(size_t)NS*128], g_xq1l[(size_t)NS*128];
__device__ float  g_xs1[NS];
__device__ int8_t g_xq2h[(size_t)NS*128], g_xq2l[(size_t)NS*128];
__device__ float  g_xs2[NS];
__device__ int8_t g_q0h[(size_t)NS*512],  g_q0l[(size_t)NS*512];
__device__ float  g_s0[NS];
__device__ float  g_act[(size_t)NS*512];
__device__ float  g_bufC[(size_t)NS*NOUTP];
__device__ int8_t g_w1h[2][512*128], g_w1l[2][512*128];
__device__ int8_t g_w2h[2][512*512], g_w2l[2][512*512];
__device__ int8_t g_w3h[2][512*512], g_w3l[2][512*512];
__device__ int8_t g_w4h[2][768*512], g_w4l[2][768*512];
__device__ float  g_ws1[2][512], g_ws2[2][512], g_ws3[2][512], g_ws4[2][768];
__device__ float  g_b4p[2][768];

// ================= helpers =================
__device__ __forceinline__ uint32_t smem_u32(const void* p) {
    uint32_t a;
    asm("{ .reg .u64 t; cvta.to.shared.u64 t, %1; cvt.u32.u64 %0, t; }" : "=r"(a) : "l"(p));
    return a;
}
#define SWZ(x) ((x) ^ (((x) >> 3) & 0x70))

#define CP16(dst, src) asm volatile("cp.async.cg.shared.global [%0], [%1], 16;" :: "r"(dst), "l"(src))
#define CP_COMMIT()    asm volatile("cp.async.commit_group;" ::: "memory")
#define CP_WAIT(N)     asm volatile("cp.async.wait_group %0;" :: "n"(N) : "memory")

#define LDSM4(r, a) \
    asm volatile("ldmatrix.sync.aligned.m8n8.x4.shared.b16 {%0,%1,%2,%3}, [%4];" \
        : "=r"((r)[0]), "=r"((r)[1]), "=r"((r)[2]), "=r"((r)[3]) : "r"(a))

#define MMAI8(c, a, b0, b1) \
    asm volatile("mma.sync.aligned.m16n8k32.row.col.s32.s8.s8.s32 " \
        "{%0,%1,%2,%3}, {%4,%5,%6,%7}, {%8,%9}, {%0,%1,%2,%3};" \
        : "+r"((c)[0]), "+r"((c)[1]), "+r"((c)[2]), "+r"((c)[3]) \
        : "r"((a)[0]), "r"((a)[1]), "r"((a)[2]), "r"((a)[3]), "r"(b0), "r"(b1))

// ================= int8 split GEMM (identical to R12) =================
template <int KT, int ACT>
__global__ void __launch_bounds__(NTHR, 2) gemm_i8(
    const int8_t* __restrict__ Aq, const int8_t* __restrict__ Aql,
    const float* __restrict__ sA,
    const int8_t* __restrict__ Bq, const int8_t* __restrict__ Bql,
    const float* __restrict__ sB,
    const float* __restrict__ bias,
    float* __restrict__ C, int ldc)
{
    extern __shared__ __align__(1024) char smem[];
    const uint32_t sb_ = smem_u32(smem);
    const int tid  = threadIdx.x;
    const int wid  = tid >> 5;
    const int l    = tid & 31;
    const int wm   = wid & 1;
    const int wn   = wid >> 1;
    const int row0 = blockIdx.y * BM;
    const int col0 = blockIdx.x * BN;
    const int lda  = KT * BKB;

    int acc1[4][4][4], acc2[4][4][4];
#pragma unroll
    for (int i = 0; i < 4; i++)
#pragma unroll
        for (int j = 0; j < 4; j++)
#pragma unroll
            for (int q = 0; q < 4; q++) { acc1[i][j][q] = 0; acc2[i][j][q] = 0; }

    auto load_tile = [&](int s, int m) {
        const uint32_t sbase = sb_ + s * STAGE;
        const int koff = m * BKB;
#pragma unroll
        for (int i = 0; i < 8; i++) {
            int c = tid + i * NTHR;
            int r = c >> 3, q = c & 7;
            uint32_t off = SWZ(r * 128 + q * 16);
            const size_t ga = (size_t)(row0 + r) * lda + koff + q * 16;
            CP16(sbase + SAH + off, Aq + ga);
            CP16(sbase + SAL + off, Aql + ga);
        }
#pragma unroll
        for (int i = 0; i < 4; i++) {
            int c = tid + i * NTHR;
            int n = c >> 3, q = c & 7;
            uint32_t off = SWZ(n * 128 + q * 16);
            const size_t gb = (size_t)(col0 + n) * lda + koff + q * 16;
            CP16(sbase + SBH + off, Bq + gb);
            CP16(sbase + SBL + off, Bql + gb);
        }
    };

    auto compute = [&](int s) {
        const uint32_t AHB = sb_ + s * STAGE + SAH;
        const uint32_t ALB = sb_ + s * STAGE + SAL;
        const uint32_t BHB = sb_ + s * STAGE + SBH;
        const uint32_t BLB = sb_ + s * STAGE + SBL;
#pragma unroll
        for (int ksl = 0; ksl < 4; ksl++) {
            uint32_t ah[4][4], al[4][4], bh[2][4], bl[2][4];
#pragma unroll
            for (int j16 = 0; j16 < 2; j16++) {
                int n = wn * 32 + j16 * 16 + (l & 7) + ((l >> 4) << 3);
                int colb = ksl * 32 + ((l >> 3) & 1) * 16;
                uint32_t sw = (uint32_t)((n & 7) << 4);
                LDSM4(bh[j16], BHB + n * 128 + (colb ^ sw));
                LDSM4(bl[j16], BLB + n * 128 + (colb ^ sw));
            }
#pragma unroll
            for (int i = 0; i < 4; i++) {
                int row = wm * 64 + i * 16 + (l & 15);
                int colb = ksl * 32 + (l >> 4) * 16;
                uint32_t sw = (uint32_t)((row & 7) << 4);
                LDSM4(ah[i], AHB + row * 128 + (colb ^ sw));
                LDSM4(al[i], ALB + row * 128 + (colb ^ sw));
            }
#pragma unroll
            for (int i = 0; i < 4; i++)
#pragma unroll
                for (int j16 = 0; j16 < 2; j16++)
#pragma unroll
                    for (int hf = 0; hf < 2; hf++)
                        MMAI8(acc1[i][j16 * 2 + hf], ah[i], bh[j16][hf*2], bh[j16][hf*2+1]);
#pragma unroll
            for (int i = 0; i < 4; i++)
#pragma unroll
                for (int j16 = 0; j16 < 2; j16++)
#pragma unroll
                    for (int hf = 0; hf < 2; hf++)
                        MMAI8(acc2[i][j16 * 2 + hf], ah[i], bl[j16][hf*2], bl[j16][hf*2+1]);
#pragma unroll
            for (int i = 0; i < 4; i++)
#pragma unroll
                for (int j16 = 0; j16 < 2; j16++)
#pragma unroll
                    for (int hf = 0; hf < 2; hf++)
                        MMAI8(acc2[i][j16 * 2 + hf], al[i], bh[j16][hf*2], bh[j16][hf*2+1]);
        }
    };

    load_tile(0, 0); CP_COMMIT();
#pragma unroll
    for (int kt = 0; kt < KT; kt++) {
        CP_WAIT(0);
        __syncthreads();
        if (kt + 1 < KT) { load_tile((kt + 1) & 1, kt + 1); CP_COMMIT(); }
        compute(kt & 1);
    }

#pragma unroll
    for (int i = 0; i < 4; i++) {
        const int r0 = row0 + wm * 64 + i * 16 + (l >> 2);
        const float sa0 = sA[r0], sa1 = sA[r0 + 8];
#pragma unroll
        for (int j = 0; j < 4; j++) {
            const int c = col0 + wn * 32 + j * 8 + (l & 3) * 2;
            const float sb0 = sB[c], sb1 = sB[c + 1];
            const float b0 = bias[c], b1 = bias[c + 1];
            float f0 = fmaf((float)acc1[i][j][0], 16384.f, (float)acc2[i][j][0] * 128.f);
            float f1 = fmaf((float)acc1[i][j][1], 16384.f, (float)acc2[i][j][1] * 128.f);
            float f2 = fmaf((float)acc1[i][j][2], 16384.f, (float)acc2[i][j][2] * 128.f);
            float f3 = fmaf((float)acc1[i][j][3], 16384.f, (float)acc2[i][j][3] * 128.f);
            float v0 = fmaf(f0, sa0 * sb0, b0);
            float v1 = fmaf(f1, sa0 * sb1, b1);
            float v2 = fmaf(f2, sa1 * sb0, b0);
            float v3 = fmaf(f3, sa1 * sb1, b1);
            if (ACT) {
                v0 = (v0 > 0.f) ? v0 : 0.2f * v0;
                v1 = (v1 > 0.f) ? v1 : 0.2f * v1;
                v2 = (v2 > 0.f) ? v2 : 0.2f * v2;
                v3 = (v3 > 0.f) ? v3 : 0.2f * v3;
            }
            *(float2*)(C + (size_t)r0 * ldc + c)       = make_float2(v0, v1);
            *(float2*)(C + (size_t)(r0 + 8) * ldc + c) = make_float2(v2, v3);
        }
    }
}

// ================= quant helpers =================
__device__ __forceinline__ void quant1(float v, float inv, float sa128,
                                       int8_t& h8, int8_t& l8) {
    int h = __float2int_rn(v * inv * (1.f / 128.f));
    float r = fmaf(-(float)h, sa128, v);
    int lo = __float2int_rn(r * inv);
    h8 = (int8_t)h; l8 = (int8_t)lo;
}

// vectorized activation quant: warp per row, float4/char4, NG = kpad/128
template <int NG>
__global__ void qact(const float* __restrict__ in, int inld, int ncols,
                     int8_t* __restrict__ qh, int8_t* __restrict__ ql,
                     float* __restrict__ scale)
{
    const int warp = (blockIdx.x * blockDim.x + threadIdx.x) >> 5;
    const int lane = threadIdx.x & 31;
    if (warp >= NS) return;
    const float* rp = in + (size_t)warp * inld;
    float4 v[NG];
    float amax = 0.f;
#pragma unroll
    for (int g = 0; g < NG; g++) {
        int c = g * 128 + lane * 4;
        v[g] = (c < ncols) ? *(const float4*)(rp + c) : make_float4(0.f, 0.f, 0.f, 0.f);
        amax = fmaxf(amax, fmaxf(fmaxf(fabsf(v[g].x), fabsf(v[g].y)),
                                 fmaxf(fabsf(v[g].z), fabsf(v[g].w))));
    }
#pragma unroll
    for (int off = 16; off > 0; off >>= 1)
        amax = fmaxf(amax, __shfl_xor_sync(0xffffffffu, amax, off));
    amax = fmaxf(amax, 1e-20f);
    const float sa    = amax * (1.f / 16256.f);
    const float inv   = 16256.f / amax;
    const float sa128 = sa * 128.f;
    const size_t base = (size_t)warp * (NG * 128);
#pragma unroll
    for (int g = 0; g < NG; g++) {
        int c = g * 128 + lane * 4;
        char4 h4, l4;
        quant1(v[g].x, inv, sa128, (int8_t&)h4.x, (int8_t&)l4.x);
        quant1(v[g].y, inv, sa128, (int8_t&)h4.y, (int8_t&)l4.y);
        quant1(v[g].z, inv, sa128, (int8_t&)h4.z, (int8_t&)l4.z);
        quant1(v[g].w, inv, sa128, (int8_t&)h4.w, (int8_t&)l4.w);
        *(char4*)(qh + base + c) = h4;
        *(char4*)(ql + base + c) = l4;
    }
    if (lane == 0) scale[warp] = sa;   // <-- THE FIX (was dropped in R13)
}

// ================= merged prep: x-quant (NS warps) + weight quant (4608 warps) =================
struct QWArgs {
    const float* W[8];
    const float* b4[2];
    int8_t* H[8];
    int8_t* L8[8];
    float*  S[8];
    float*  bp[2];
};

__global__ void prep_all(QWArgs a, const float* __restrict__ x,
                         int8_t* __restrict__ xqh, int8_t* __restrict__ xql,
                         float* __restrict__ xs)
{
    int gw = (int)((blockIdx.x * blockDim.x + threadIdx.x) >> 5);
    const int lane = threadIdx.x & 31;

    if (gw < NS) {
        const float* rp = x + (size_t)gw * 64;
        int c = lane * 4;
        float4 v = (c < HALF) ? *(const float4*)(rp + c) : make_float4(0.f, 0.f, 0.f, 0.f);
        float amax = fmaxf(fmaxf(fabsf(v.x), fabsf(v.y)), fmaxf(fabsf(v.z), fabsf(v.w)));
#pragma unroll
        for (int off = 16; off > 0; off >>= 1)
            amax = fmaxf(amax, __shfl_xor_sync(0xffffffffu, amax, off));
        amax = fmaxf(amax, 1e-20f);
        const float sa    = amax * (1.f / 16256.f);
        const float inv   = 16256.f / amax;
        const float sa128 = sa * 128.f;
        char4 h4, l4;
        quant1(v.x, inv, sa128, (int8_t&)h4.x, (int8_t&)l4.x);
        quant1(v.y, inv, sa128, (int8_t&)h4.y, (int8_t&)l4.y);
        quant1(v.z, inv, sa128, (int8_t&)h4.z, (int8_t&)l4.z);
        quant1(v.w, inv, sa128, (int8_t&)h4.w, (int8_t&)l4.w);
        const size_t base = (size_t)gw * 128 + c;
        *(char4*)(xqh + base) = h4;
        *(char4*)(xql + base) = l4;
        if (lane == 0) xs[gw] = sa;
        return;
    }
    gw -= NS;
    if (gw >= 4608) return;
    const int cc = (gw >= 2304) ? 1 : 0;
    int off = gw - cc * 2304;
    int seg, n, K, N, Kpad;
    if (off < 512)       { seg = 0; n = off;        K = 32;  N = 512; Kpad = 128; }
    else if (off < 1024) { seg = 1; n = off - 512;  K = 512; N = 512; Kpad = 512; }
    else if (off < 1536) { seg = 2; n = off - 1024; K = 512; N = 512; Kpad = 512; }
    else                 { seg = 3; n = off - 1536; K = 512; N = 736; Kpad = 512; }
    const int widx = cc * 4 + seg;
    const float* W = a.W[widx];
    const int nk = Kpad >> 5;

    float vals[16];
    float amax = 0.f;
#pragma unroll 16
    for (int i = 0; i < 16; i++) {
        if (i < nk) {
            int k = lane + 32 * i;
            float v = (k < K && n < N) ? W[(size_t)k * N + n] : 0.f;
            vals[i] = v;
            amax = fmaxf(amax, fabsf(v));
        }
    }
#pragma unroll
    for (int o = 16; o > 0; o >>= 1)
        amax = fmaxf(amax, __shfl_xor_sync(0xffffffffu, amax, o));
    amax = fmaxf(amax, 1e-20f);
    const float sbv   = amax * (1.f / 16256.f);
    const float inv   = 16256.f / amax;
    const float sb128 = sbv * 128.f;
    const size_t base = (size_t)n * Kpad;
#pragma unroll 16
    for (int i = 0; i < 16; i++) {
        if (i < nk) {
            int k = lane + 32 * i;
            int8_t h8, l8;
            quant1(vals[i], inv, sb128, h8, l8);
            a.H[widx][base + k]  = h8;
            a.L8[widx][base + k] = l8;
        }
    }
    if (lane == 0) {
        a.S[widx][n] = sbv;
        if (seg == 3) a.bp[cc][n] = (n < 736) ? a.b4[cc][n] : 0.f;
    }
}

// ================= spline (identical numerics to R12) =================
__device__ __forceinline__ float softplusf(float x) {
    return (x > 0.f) ? (x + log1pf(expf(-x))) : log1pf(expf(x));
}

__global__ void __launch_bounds__(256) spline_kernel(
    const float* __restrict__ y, int ldy,
    const float* __restrict__ cond,
    float* __restrict__ out_y, int ldo,
    float* __restrict__ logdet, int add,
    int8_t* __restrict__ qh, int8_t* __restrict__ ql, float* __restrict__ qs)
{
    const int gid = blockIdx.x * 256 + threadIdx.x;
    const int s   = gid >> 5;
    const int dim = gid & 31;
    if (s >= NS) return;

    const float* p = cond + (size_t)s * NOUTP + dim * 23;
    const float x = y[(size_t)s * ldy + dim];

    float rw[KB], rh[KB];
#pragma unroll
    for (int i = 0; i < KB; i++) rw[i] = p[i];
#pragma unroll
    for (int i = 0; i < KB; i++) rh[i] = p[KB + i];

    float cw[KB + 1], wid[KB];
    {
        float m = rw[0];
#pragma unroll
        for (int i = 1; i < KB; i++) m = fmaxf(m, rw[i]);
        float s1 = 0.f, e[KB];
#pragma unroll
        for (int i = 0; i < KB; i++) { e[i] = expf(rw[i] - m); s1 += e[i]; }
        float inv1 = 1.f / s1, Wv[KB];
#pragma unroll
        for (int i = 0; i < KB; i++) Wv[i] = 2.f * TB * e[i] * inv1;
        float m2 = Wv[0];
#pragma unroll
        for (int i = 1; i < KB; i++) m2 = fmaxf(m2, Wv[i]);
        float s2 = 0.f;
#pragma unroll
        for (int i = 0; i < KB; i++) { e[i] = expf(Wv[i] - m2); s2 += e[i]; }
        float inv2 = 1.f / s2;
        float run = 0.f;
        cw[0] = -TB;
#pragma unroll
        for (int i = 0; i < KB; i++) {
            float w = 0.001f + (1.f - 0.001f * KB) * e[i] * inv2;
            run += w;
            cw[i + 1] = 2.f * TB * run - TB;
        }
        cw[KB] = TB;
#pragma unroll
        for (int i = 0; i < KB; i++) wid[i] = cw[i + 1] - cw[i];
    }

    float ch[KB + 1], hei[KB];
    {
        float m = rh[0];
#pragma unroll
        for (int i = 1; i < KB; i++) m = fmaxf(m, rh[i]);
        float s1 = 0.f, e[KB];
#pragma unroll
        for (int i = 0; i < KB; i++) { e[i] = expf(rh[i] - m); s1 += e[i]; }
        float inv1 = 1.f / s1, Hv[KB];
#pragma unroll
        for (int i = 0; i < KB; i++) Hv[i] = 2.f * TB * e[i] * inv1;
        float m2 = Hv[0];
#pragma unroll
        for (int i = 1; i < KB; i++) m2 = fmaxf(m2, Hv[i]);
        float s2 = 0.f;
#pragma unroll
        for (int i = 0; i < KB; i++) { e[i] = expf(Hv[i] - m2); s2 += e[i]; }
        float inv2 = 1.f / s2;
        float run = 0.f;
        ch[0] = -TB;
#pragma unroll
        for (int i = 0; i < KB; i++) {
            float h = 0.001f + (1.f - 0.001f * KB) * e[i] * inv2;
            run += h;
            ch[i + 1] = 2.f * TB * run - TB;
        }
        ch[KB] = TB;
#pragma unroll
        for (int i = 0; i < KB; i++) hei[i] = ch[i + 1] - ch[i];
    }

    float der[KB + 1];
    {
        const float CONST = 0.5397432446f;
        der[0] = 0.001f + softplusf(CONST);
        der[KB] = der[0];
#pragma unroll
        for (int i = 0; i < KB - 1; i++)
            der[i + 1] = 0.001f + softplusf(softplusf(p[2 * KB + i]));
    }

    const bool inside = (x >= -TB) && (x <= TB);
    const float xc = fminf(fmaxf(x, -TB), TB);
    int cnt = 0;
#pragma unroll
    for (int j = 0; j <= KB; j++) {
        float ce = cw[j] + ((j == KB) ? 1e-6f : 0.f);
        cnt += (xc >= ce) ? 1 : 0;
    }
    int idx = min(max(cnt - 1, 0), KB - 1);

    float in_cw = 0.f, in_w = 1.f, in_ch = 0.f, in_h = 1.f, in_der = 1.f, in_der1 = 1.f;
#pragma unroll
    for (int j = 0; j < KB; j++) {
        if (j == idx) {
            in_cw = cw[j]; in_w = wid[j]; in_ch = ch[j]; in_h = hei[j];
            in_der = der[j]; in_der1 = der[j + 1];
        }
    }
    const float in_d = in_h / in_w;
    const float theta = (xc - in_cw) / in_w;
    const float t1mt  = theta * (1.f - theta);
    const float num   = in_h * (in_d * theta * theta + in_der * t1mt);
    const float den   = in_d + (in_der + in_der1 - 2.f * in_d) * t1mt;
    const float outv  = in_ch + num / den;
    const float omt   = 1.f - theta;
    const float dnum  = in_d * in_d * (in_der1 * theta * theta + 2.f * in_d * t1mt + in_der * omt * omt);
    float lad = logf(dnum) - 2.f * logf(den);

    const float fv = inside ? outv : x;
    out_y[(size_t)s * ldo + dim] = fv;
    lad = inside ? lad : 0.f;

    if (qh) {
        float amax = fabsf(fv);
#pragma unroll
        for (int off = 16; off > 0; off >>= 1)
            amax = fmaxf(amax, __shfl_xor_sync(0xffffffffu, amax, off));
        amax = fmaxf(amax, 1e-20f);
        const float sa    = amax * (1.f / 16256.f);
        const float inv   = 16256.f / amax;
        const float sa128 = sa * 128.f;
        int8_t h8, l8;
        quant1(fv, inv, sa128, h8, l8);
        const size_t base = (size_t)s * 128 + dim;
        qh[base] = h8;  ql[base] = l8;
        qh[base + 32] = 0; ql[base + 32] = 0;
        qh[base + 64] = 0; ql[base + 64] = 0;
        qh[base + 96] = 0; ql[base + 96] = 0;
        if (dim == 0) qs[s] = sa;
    }

#pragma unroll
    for (int off = 16; off > 0; off >>= 1)
        lad += __shfl_down_sync(0xffffffffu, lad, off);
    if (dim == 0) {
        if (add) logdet[s] += lad;
        else     logdet[s]  = lad;
    }
}

// ================= launch =================
extern "C" void kernel_launch(void* const* d_in, const int* in_sizes, int n_in,
                              void* d_out, int out_size)
{
    const float* x = (const float*)d_in[0];
    const float* w[2][4] = {{(const float*)d_in[1], (const float*)d_in[3], (const float*)d_in[5], (const float*)d_in[7]},
                            {(const float*)d_in[9], (const float*)d_in[11], (const float*)d_in[13], (const float*)d_in[15]}};
    const float* bb[2][4] = {{(const float*)d_in[2], (const float*)d_in[4], (const float*)d_in[6], (const float*)d_in[8]},
                             {(const float*)d_in[10], (const float*)d_in[12], (const float*)d_in[14], (const float*)d_in[16]}};

    float* out    = (float*)d_out;
    float* logdet = out + (size_t)NS * 64;

    int8_t *xq1h, *xq1l, *xq2h, *xq2l, *q0h, *q0l;
    float  *xs1, *xs2, *s0, *actF, *bufC, *b4p;
    int8_t *w1h, *w1l, *w2h, *w2l, *w3h, *w3l, *w4h, *w4l;
    float  *ws1, *ws2, *ws3, *ws4;
    cudaGetSymbolAddress((void**)&xq1h, g_xq1h); cudaGetSymbolAddress((void**)&xq1l, g_xq1l);
    cudaGetSymbolAddress((void**)&xs1, g_xs1);
    cudaGetSymbolAddress((void**)&xq2h, g_xq2h); cudaGetSymbolAddress((void**)&xq2l, g_xq2l);
    cudaGetSymbolAddress((void**)&xs2, g_xs2);
    cudaGetSymbolAddress((void**)&q0h, g_q0h);   cudaGetSymbolAddress((void**)&q0l, g_q0l);
    cudaGetSymbolAddress((void**)&s0, g_s0);
    cudaGetSymbolAddress((void**)&actF, g_act);
    cudaGetSymbolAddress((void**)&bufC, g_bufC);
    cudaGetSymbolAddress((void**)&w1h, g_w1h); cudaGetSymbolAddress((void**)&w1l, g_w1l);
    cudaGetSymbolAddress((void**)&w2h, g_w2h); cudaGetSymbolAddress((void**)&w2l, g_w2l);
    cudaGetSymbolAddress((void**)&w3h, g_w3h); cudaGetSymbolAddress((void**)&w3l, g_w3l);
    cudaGetSymbolAddress((void**)&w4h, g_w4h); cudaGetSymbolAddress((void**)&w4l, g_w4l);
    cudaGetSymbolAddress((void**)&ws1, g_ws1); cudaGetSymbolAddress((void**)&ws2, g_ws2);
    cudaGetSymbolAddress((void**)&ws3, g_ws3); cudaGetSymbolAddress((void**)&ws4, g_ws4);
    cudaGetSymbolAddress((void**)&b4p, g_b4p);

    cudaFuncSetAttribute(gemm_i8<1,1>, cudaFuncAttributeMaxDynamicSharedMemorySize, SMEM_TOTAL);
    cudaFuncSetAttribute(gemm_i8<4,1>, cudaFuncAttributeMaxDynamicSharedMemorySize, SMEM_TOTAL);
    cudaFuncSetAttribute(gemm_i8<4,0>, cudaFuncAttributeMaxDynamicSharedMemorySize, SMEM_TOTAL);

    QWArgs qa;
    for (int c = 0; c < 2; c++) {
        for (int s = 0; s < 4; s++) qa.W[c*4 + s] = w[c][s];
        qa.b4[c] = bb[c][3];
        qa.H[c*4 + 0] = w1h + c*512*128; qa.L8[c*4 + 0] = w1l + c*512*128; qa.S[c*4 + 0] = ws1 + c*512;
        qa.H[c*4 + 1] = w2h + c*512*512; qa.L8[c*4 + 1] = w2l + c*512*512; qa.S[c*4 + 1] = ws2 + c*512;
        qa.H[c*4 + 2] = w3h + c*512*512; qa.L8[c*4 + 2] = w3l + c*512*512; qa.S[c*4 + 2] = ws3 + c*512;
        qa.H[c*4 + 3] = w4h + c*768*512; qa.L8[c*4 + 3] = w4l + c*768*512; qa.S[c*4 + 3] = ws4 + c*768;
        qa.bp[c] = b4p + c*768;
    }
    prep_all<<<(NS + 4608 + 7) / 8, 256>>>(qa, x, xq1h, xq1l, xs1);

    const dim3 gemmBlk(NTHR);
    const dim3 g512(NHID / BN, NS / BM);     // (8, 512)
    const dim3 g768(NOUTP / BN, NS / BM);    // (12, 512)
    const dim3 splineBlk(256);
    const int splineBlocks = (NS * 32) / 256;
    const int qactBlocks = NS / 8;

    for (int c = 0; c < 2; c++) {
        const int8_t* inH = (c == 0) ? xq1h : xq2h;
        const int8_t* inL = (c == 0) ? xq1l : xq2l;
        const float*  inS = (c == 0) ? xs1  : xs2;

        gemm_i8<1,1><<<g512, gemmBlk, SMEM_TOTAL>>>(inH, inL, inS,
            w1h + c*512*128, w1l + c*512*128, ws1 + c*512, bb[c][0], actF, NHID);
        qact<4><<<qactBlocks, 256>>>(actF, NHID, NHID, q0h, q0l, s0);

        gemm_i8<4,1><<<g512, gemmBlk, SMEM_TOTAL>>>(q0h, q0l, s0,
            w2h + c*512*512, w2l + c*512*512, ws2 + c*512, bb[c][1], actF, NHID);
        qact<4><<<qactBlocks, 256>>>(actF, NHID, NHID, q0h, q0l, s0);

        gemm_i8<4,1><<<g512, gemmBlk, SMEM_TOTAL>>>(q0h, q0l, s0,
            w3h + c*512*512, w3l + c*512*512, ws3 + c*512, bb[c][2], actF, NHID);
        qact<4><<<qactBlocks, 256>>>(actF, NHID, NHID, q0h, q0l, s0);

        gemm_i8<4,0><<<g768, gemmBlk, SMEM_TOTAL>>>(q0h, q0l, s0,
            w4h + c*768*512, w4l + c*768*512, ws4 + c*768, b4p + c*768, bufC, NOUTP);

        if (c == 0)
            spline_kernel<<<splineBlocks, splineBlk>>>(x + HALF, 64, bufC,
                out + HALF, 64, logdet, 0, xq2h, xq2l, xs2);
        else
            spline_kernel<<<splineBlocks, splineBlk>>>(x, 64, bufC,
                out, 64, logdet, 1, nullptr, nullptr, nullptr);
    }
}